// round 14
// baseline (speedup 1.0000x reference)
#include <cuda_runtime.h>
#include <cuda_bf16.h>
#include <cstdint>
#include <cstddef>

#define BB 128
#define TT 64
#define HH 256
#define VV 128
#define G3H 768

// ---------------- persistent scratch ----------------
__device__ float g_xp [BB*TT*G3H];     // input projections (both layers, reused)
__device__ float g_seq[BB*TT*HH];      // layer-0 output
__device__ float g_enc[BB*TT*HH];      // layer-1 output (encoder)
__device__ float g_Wa [BB*TT*HH];
__device__ float g_Ua [BB*TT*HH];
__device__ float g_ctx[BB*TT*HH];

// ---------------- helpers ----------------
union F2U { float2 f; unsigned long long u; };

__device__ __forceinline__ float2 ffma2(float2 a, float2 b, float2 c) {
    F2U A, B, C, D; A.f = a; B.f = b; C.f = c;
    asm("fma.rn.f32x2 %0, %1, %2, %3;" : "=l"(D.u) : "l"(A.u), "l"(B.u), "l"(C.u));
    return D.f;
}

__device__ __forceinline__ float4 ffma4(float a, float4 b, float4 c) {
    float2 p = ffma2(make_float2(a, a), make_float2(b.x, b.y), make_float2(c.x, c.y));
    float2 q = ffma2(make_float2(a, a), make_float2(b.z, b.w), make_float2(c.z, c.w));
    return make_float4(p.x, p.y, q.x, q.y);
}

__device__ __forceinline__ float tanha(float x) {
    float y; asm("tanh.approx.f32 %0, %1;" : "=f"(y) : "f"(x)); return y;
}

__device__ __forceinline__ float sigm(float x) {
    return 1.f / (1.f + __expf(-x));
}

__device__ __forceinline__ uint32_t smem_u32(const void* p) {
    uint32_t a;
    asm("{ .reg .u64 t; cvta.to.shared.u64 t, %1; cvt.u32.u64 %0, t; }" : "=r"(a) : "l"(p));
    return a;
}

#define MBARRIER_INIT(addr, cnt) \
    asm volatile("mbarrier.init.shared.b64 [%0], %1;" :: "r"(addr), "r"(cnt) : "memory")

#define MBARRIER_EXPECT_TX(addr, tx) \
    asm volatile("mbarrier.arrive.expect_tx.shared.b64 _, [%0], %1;" :: "r"(addr), "r"(tx) : "memory")

#define MBARRIER_WAIT_PARITY(addr, par) do {                                        \
    uint32_t _m = (addr); uint32_t _p = (par); uint32_t _done;                      \
    asm volatile("{\n\t.reg .pred p;\n\t"                                           \
        "mbarrier.try_wait.parity.acquire.cta.shared::cta.b64 p, [%1], %2;\n\t"     \
        "selp.b32 %0, 1, 0, p;\n\t}"                                                \
        : "=r"(_done) : "r"(_m), "r"(_p) : "memory");                               \
    if (!_done) {                                                                   \
        asm volatile("{\n\t.reg .pred P1;\n\t"                                      \
            "WL_%=:\n\t"                                                            \
            "mbarrier.try_wait.parity.acquire.cta.shared::cta.b64 P1, [%0], %1, 0x989680;\n\t" \
            "@P1 bra.uni WD_%=;\n\t"                                                \
            "bra.uni WL_%=;\n\t"                                                    \
            "WD_%=:\n\t}" :: "r"(_m), "r"(_p) : "memory");                          \
    }                                                                               \
} while (0)

#define ST_ASYNC_B32(raddr, uval, rmbar) \
    asm volatile("st.async.shared::cluster.mbarrier::complete_tx::bytes.b32 [%0], %1, [%2];" \
        :: "r"(raddr), "r"(uval), "r"(rmbar) : "memory")

#define MAPA_U32(dst, laddr, rank) \
    asm("mapa.shared::cluster.u32 %0, %1, %2;" : "=r"(dst) : "r"(laddr), "r"(rank))

#define CLUSTER_SYNC() do {                                              \
    asm volatile("barrier.cluster.arrive.aligned;" ::: "memory");        \
    asm volatile("barrier.cluster.wait.aligned;" ::: "memory");          \
} while (0)

// ---------------- GEMM: C[m,n] = sum_k A[m,k]*W[n,k] (+bias | +=C) ----------------
// BM=128 BN=128 BK=16, 256 threads, 8x8 per thread, f32x2 FMA, register-staged
// k-tile pipelining. gather != null: A row m is A + gather[m]*lda.
__global__ void __launch_bounds__(256)
gemm_k(const float* __restrict__ A, int lda, const int* __restrict__ gather,
       const float* __restrict__ W, int ldw,
       const float* __restrict__ bias,
       float* __restrict__ C, int ldc, int K, int accumulate)
{
    __shared__ float As[16 * 132];
    __shared__ float Bs[16 * 132];

    const int tid = threadIdx.x;
    const int tx = tid & 15;           // n-octet
    const int ty = tid >> 4;           // m-octet
    const int mbase = blockIdx.x * 128;
    const int nbase = blockIdx.y * 128;

    const int ra = tid >> 2;           // rows ra and ra+64 (A and W)
    const int c4 = tid & 3;            // float4 column within 16-wide k-tile
    const int m0 = mbase + ra;
    const int m1 = mbase + ra + 64;
    const float* arow0 = A + (size_t)(gather ? gather[m0] : m0) * lda;
    const float* arow1 = A + (size_t)(gather ? gather[m1] : m1) * lda;
    const float* wrow0 = W + (size_t)(nbase + ra) * ldw;
    const float* wrow1 = W + (size_t)(nbase + ra + 64) * ldw;

    float4 acc[8][2];
#pragma unroll
    for (int i = 0; i < 8; ++i) {
        acc[i][0] = make_float4(0.f, 0.f, 0.f, 0.f);
        acc[i][1] = make_float4(0.f, 0.f, 0.f, 0.f);
    }

    const int ktiles = K >> 4;
    float4 Av0 = __ldg((const float4*)(arow0 + c4 * 4));
    float4 Av1 = __ldg((const float4*)(arow1 + c4 * 4));
    float4 Bv0 = __ldg((const float4*)(wrow0 + c4 * 4));
    float4 Bv1 = __ldg((const float4*)(wrow1 + c4 * 4));

    for (int kt = 0; kt < ktiles; ++kt) {
        As[(c4 * 4 + 0) * 132 + ra]      = Av0.x;
        As[(c4 * 4 + 1) * 132 + ra]      = Av0.y;
        As[(c4 * 4 + 2) * 132 + ra]      = Av0.z;
        As[(c4 * 4 + 3) * 132 + ra]      = Av0.w;
        As[(c4 * 4 + 0) * 132 + ra + 64] = Av1.x;
        As[(c4 * 4 + 1) * 132 + ra + 64] = Av1.y;
        As[(c4 * 4 + 2) * 132 + ra + 64] = Av1.z;
        As[(c4 * 4 + 3) * 132 + ra + 64] = Av1.w;
        Bs[(c4 * 4 + 0) * 132 + ra]      = Bv0.x;
        Bs[(c4 * 4 + 1) * 132 + ra]      = Bv0.y;
        Bs[(c4 * 4 + 2) * 132 + ra]      = Bv0.z;
        Bs[(c4 * 4 + 3) * 132 + ra]      = Bv0.w;
        Bs[(c4 * 4 + 0) * 132 + ra + 64] = Bv1.x;
        Bs[(c4 * 4 + 1) * 132 + ra + 64] = Bv1.y;
        Bs[(c4 * 4 + 2) * 132 + ra + 64] = Bv1.z;
        Bs[(c4 * 4 + 3) * 132 + ra + 64] = Bv1.w;
        __syncthreads();

        if (kt + 1 < ktiles) {
            Av0 = __ldg((const float4*)(arow0 + (kt + 1) * 16 + c4 * 4));
            Av1 = __ldg((const float4*)(arow1 + (kt + 1) * 16 + c4 * 4));
            Bv0 = __ldg((const float4*)(wrow0 + (kt + 1) * 16 + c4 * 4));
            Bv1 = __ldg((const float4*)(wrow1 + (kt + 1) * 16 + c4 * 4));
        }

#pragma unroll
        for (int k = 0; k < 16; ++k) {
            float4 a0 = *(const float4*)&As[k * 132 + ty * 8];
            float4 a1 = *(const float4*)&As[k * 132 + ty * 8 + 4];
            float4 b0 = *(const float4*)&Bs[k * 132 + tx * 8];
            float4 b1 = *(const float4*)&Bs[k * 132 + tx * 8 + 4];
            acc[0][0] = ffma4(a0.x, b0, acc[0][0]); acc[0][1] = ffma4(a0.x, b1, acc[0][1]);
            acc[1][0] = ffma4(a0.y, b0, acc[1][0]); acc[1][1] = ffma4(a0.y, b1, acc[1][1]);
            acc[2][0] = ffma4(a0.z, b0, acc[2][0]); acc[2][1] = ffma4(a0.z, b1, acc[2][1]);
            acc[3][0] = ffma4(a0.w, b0, acc[3][0]); acc[3][1] = ffma4(a0.w, b1, acc[3][1]);
            acc[4][0] = ffma4(a1.x, b0, acc[4][0]); acc[4][1] = ffma4(a1.x, b1, acc[4][1]);
            acc[5][0] = ffma4(a1.y, b0, acc[5][0]); acc[5][1] = ffma4(a1.y, b1, acc[5][1]);
            acc[6][0] = ffma4(a1.z, b0, acc[6][0]); acc[6][1] = ffma4(a1.z, b1, acc[6][1]);
            acc[7][0] = ffma4(a1.w, b0, acc[7][0]); acc[7][1] = ffma4(a1.w, b1, acc[7][1]);
        }
        __syncthreads();
    }

    const int n0 = nbase + tx * 8;
    float4 bv0 = make_float4(0.f, 0.f, 0.f, 0.f);
    float4 bv1 = bv0;
    if (bias) { bv0 = *(const float4*)&bias[n0]; bv1 = *(const float4*)&bias[n0 + 4]; }
#pragma unroll
    for (int mi = 0; mi < 8; ++mi) {
        int m = mbase + ty * 8 + mi;
        float4* cp = (float4*)&C[(size_t)m * ldc + n0];
        float4 o0 = acc[mi][0], o1 = acc[mi][1];
        if (accumulate) {
            float4 q0 = cp[0], q1 = cp[1];
            o0.x += q0.x; o0.y += q0.y; o0.z += q0.z; o0.w += q0.w;
            o1.x += q1.x; o1.y += q1.y; o1.z += q1.z; o1.w += q1.w;
        } else {
            o0.x += bv0.x; o0.y += bv0.y; o0.z += bv0.z; o0.w += bv0.w;
            o1.x += bv1.x; o1.y += bv1.y; o1.z += bv1.z; o1.w += bv1.w;
        }
        cp[0] = o0; cp[1] = o1;
    }
}

// ---------------- GRU scan: 32 clusters x 4 CTAs, 512 threads ----------------
// Thread (j = tid>>3, kq = tid&7): one j-row x 4 batches x k-float4s {kq+8i}.
// Weights read from smem EXACTLY ONCE per CTA per step. h read directly from
// smem (b uniform per instruction, 128B-aligned stride-256 rows -> 1 phase,
// 4-way dedup across the warp's j-lanes). Only reduction shuffles remain.
// Lane kq<4 finalizes batch b=kq. h exchanged via st.async as before.
#define SCAN_WS_BYTES   (3 * 64 * 64 * 16)            // 196608
#define SCAN_HB_BYTES   (2 * 4 * 256 * 4)             // 8192, stride 256 (aligned)
#define SCAN_SMEM_BYTES (SCAN_WS_BYTES + SCAN_HB_BYTES + 16)

__global__ void __launch_bounds__(512, 1) __cluster_dims__(4, 1, 1)
scan_k(const float* __restrict__ xp, const float* __restrict__ w_hh,
       const float* __restrict__ b_hh, float* __restrict__ seq,
       float* __restrict__ hlast)
{
    extern __shared__ __align__(16) unsigned char sm_raw[];
    float4* ws = (float4*)sm_raw;                               // [3][64 j][64 f4]
    float*  hb = (float*)(sm_raw + SCAN_WS_BYTES);              // [2][4][256]
    unsigned long long* mbar =
        (unsigned long long*)(sm_raw + SCAN_WS_BYTES + SCAN_HB_BYTES);

    const int g   = blockIdx.x >> 2;
    const int tid = threadIdx.x;
    const int j   = tid >> 3;                 // 0..63  local output row
    const int kq  = tid & 7;                  // 0..7   k-slice
    uint32_t rank;
    asm("mov.u32 %0, %%cluster_ctarank;" : "=r"(rank));
    const int b0  = g * 4;
    const int jgo = (int)rank * 64 + j;       // global hidden index
    const int b_out = kq & 3;                 // batch this lane may finalize
    const bool is_out = (kq < 4);

    // ---- prologue: copy w_hh slice (row-major, identity in f4) ----
    for (int idx = tid; idx < 3 * 64 * 64; idx += 512) {
        int gg = idx >> 12;
        int jl = (idx >> 6) & 63;
        int f4 = idx & 63;
        ws[idx] = __ldg((const float4*)(w_hh +
                    (size_t)(gg * 256 + (int)rank * 64 + jl) * 256) + f4);
    }

    const float bh0 = b_hh[jgo], bh1 = b_hh[256 + jgo], bh2 = b_hh[512 + jgo];

    const uint32_t mb0 = smem_u32(&mbar[0]);
    const uint32_t myh = smem_u32(&hb[(size_t)b_out * 256 + jgo]);  // parity-0 slot
    uint32_t rh[4], rm[4];
#pragma unroll
    for (int r = 0; r < 4; ++r) { MAPA_U32(rh[r], myh, r); MAPA_U32(rm[r], mb0, r); }

    if (tid == 0) { MBARRIER_INIT(mb0, 1); MBARRIER_INIT(mb0 + 8, 1); }
    __syncthreads();
    CLUSTER_SYNC();                       // all mbars + ws live before any st.async
    if (tid == 0) {
        MBARRIER_EXPECT_TX(mb0, 4096);
        MBARRIER_EXPECT_TX(mb0 + 8, 4096);
    }

    const float* xpb = xp + (size_t)(b0 + b_out) * TT * G3H;
    const float4* wp = ws + (size_t)j * 64 + kq;     // + gg*4096 + 8i
    float hprev = 0.f;
    int ph0 = 0, ph1 = 0;

    for (int t = 0; t < TT; ++t) {
        // prefetch xp for (b_out, t) — hidden under wait + matvec
        float xr = 0.f, xz = 0.f, xn = 0.f;
        if (is_out) {
            const float* xr_p = xpb + (size_t)t * G3H;
            xr = __ldcg(xr_p + jgo);
            xz = __ldcg(xr_p + 256 + jgo);
            xn = __ldcg(xr_p + 512 + jgo);
        }

        float hr, hz, hn;
        if (t == 0) {
            hr = bh0; hz = bh1; hn = bh2;           // h == 0
        } else {
            const int ip = (t - 1) & 1;
            if (ip == 0) { MBARRIER_WAIT_PARITY(mb0, ph0);     ph0 ^= 1; }
            else         { MBARRIER_WAIT_PARITY(mb0 + 8, ph1); ph1 ^= 1; }
            if (tid == 0) MBARRIER_EXPECT_TX(mb0 + 8 * ip, 4096);  // re-arm

            const float4* h4 = (const float4*)(hb + (size_t)ip * 1024) + kq;

            float2 acc[4][3];
#pragma unroll
            for (int b = 0; b < 4; ++b)
#pragma unroll
                for (int gg = 0; gg < 3; ++gg)
                    acc[b][gg] = make_float2(0.f, 0.f);

#pragma unroll
            for (int i = 0; i < 8; ++i) {
                float4 wv0 = wp[8 * i];
                float4 wv1 = wp[4096 + 8 * i];
                float4 wv2 = wp[8192 + 8 * i];
#pragma unroll
                for (int b = 0; b < 4; ++b) {
                    float4 hv = h4[b * 64 + 8 * i];   // 128B/warp, 1 phase
                    float2 hxy = make_float2(hv.x, hv.y);
                    float2 hzw = make_float2(hv.z, hv.w);
                    acc[b][0] = ffma2(make_float2(wv0.x, wv0.y), hxy, acc[b][0]);
                    acc[b][0] = ffma2(make_float2(wv0.z, wv0.w), hzw, acc[b][0]);
                    acc[b][1] = ffma2(make_float2(wv1.x, wv1.y), hxy, acc[b][1]);
                    acc[b][1] = ffma2(make_float2(wv1.z, wv1.w), hzw, acc[b][1]);
                    acc[b][2] = ffma2(make_float2(wv2.x, wv2.y), hxy, acc[b][2]);
                    acc[b][2] = ffma2(make_float2(wv2.z, wv2.w), hzw, acc[b][2]);
                }
            }

            // horizontal + 8-way xor reduction over kq lanes (same j)
            float s[4][3];
#pragma unroll
            for (int b = 0; b < 4; ++b)
#pragma unroll
                for (int gg = 0; gg < 3; ++gg) {
                    float v = acc[b][gg].x + acc[b][gg].y;
                    v += __shfl_xor_sync(0xffffffffu, v, 1);
                    v += __shfl_xor_sync(0xffffffffu, v, 2);
                    v += __shfl_xor_sync(0xffffffffu, v, 4);
                    s[b][gg] = v;
                }

            hr = s[b_out][0] + bh0;
            hz = s[b_out][1] + bh1;
            hn = s[b_out][2] + bh2;
        }

        if (is_out) {
            const float r = sigm(xr + hr);
            const float z = sigm(xz + hz);
            const float n = tanhf(xn + r * hn);
            const float hnew = (1.f - z) * n + z * hprev;
            hprev = hnew;

            __stcg(&seq[((size_t)(b0 + b_out) * TT + t) * HH + jgo], hnew);
            if (hlast != nullptr && t == TT - 1)
                __stcg(&hlast[(size_t)(b0 + b_out) * HH + jgo], hnew);

            // broadcast my h value to all 4 CTAs' buffer[t&1]
            const uint32_t po = (uint32_t)(t & 1) * 4096u;      // 1024 floats
            const uint32_t uval = __float_as_uint(hnew);
#pragma unroll
            for (int r2 = 0; r2 < 4; ++r2)
                ST_ASYNC_B32(rh[r2] + po, uval, rm[r2] + (uint32_t)(t & 1) * 8u);
        }
    }

    // drain: consume the final phase so no st.async targets our smem after exit
    MBARRIER_WAIT_PARITY(mb0 + 8, ph1);
    CLUSTER_SYNC();
}

// ---------------- attention (CTA per batch) ----------------
#define AT_SMEM_FLOATS (2 * 64 * 260 + 64 * 68 + 256)
#define AT_SMEM_BYTES  (AT_SMEM_FLOATS * 4)

__global__ void __launch_bounds__(256, 1)
attn_k(const float* __restrict__ Wa, const float* __restrict__ Ua,
       const float* __restrict__ enc, const float* __restrict__ va,
       float* __restrict__ ctx)
{
    extern __shared__ float sm[];
    float* WA = sm;
    float* UA = sm + 64 * 260;
    float* ES = sm + 2 * 64 * 260;
    float* VS = ES + 64 * 68;

    const int b = blockIdx.x;
    const int tid = threadIdx.x;
    const float* waB = Wa + (size_t)b * 64 * 256;
    const float* uaB = Ua + (size_t)b * 64 * 256;

    for (int idx = tid; idx < 4096; idx += 256) {
        int k = idx >> 6, h4 = idx & 63;
        float4 w4 = __ldg((const float4*)waB + idx);
        *(float4*)&WA[k * 260 + ((h4 ^ (k & 7)) << 2)] = w4;   // xor swizzle
        float4 u4 = __ldg((const float4*)uaB + idx);
        *(float4*)&UA[k * 260 + (h4 << 2)] = u4;
    }
    if (tid < 64) *(float4*)&VS[tid * 4] = __ldg((const float4*)va + tid);
    __syncthreads();

    const int tq = tid >> 3, kq = tid & 7;
    const int t0 = tq * 2;
    float e0[8], e1[8];
#pragma unroll
    for (int i = 0; i < 8; ++i) { e0[i] = 0.f; e1[i] = 0.f; }

    for (int h4 = 0; h4 < 64; ++h4) {
        float4 v4 = *(const float4*)&VS[h4 * 4];
        float4 uA = *(const float4*)&UA[t0 * 260 + h4 * 4];
        float4 uB = *(const float4*)&UA[(t0 + 1) * 260 + h4 * 4];
#pragma unroll
        for (int i = 0; i < 8; ++i) {
            int k = i * 8 + kq;
            float4 w4 = *(const float4*)&WA[k * 260 + ((h4 ^ kq) << 2)];
            e0[i] += tanha(w4.x + uA.x) * v4.x + tanha(w4.y + uA.y) * v4.y
                   + tanha(w4.z + uA.z) * v4.z + tanha(w4.w + uA.w) * v4.w;
            e1[i] += tanha(w4.x + uB.x) * v4.x + tanha(w4.y + uB.y) * v4.y
                   + tanha(w4.z + uB.z) * v4.z + tanha(w4.w + uB.w) * v4.w;
        }
    }
#pragma unroll
    for (int i = 0; i < 8; ++i) {
        ES[t0 * 68 + i * 8 + kq] = e0[i];
        ES[(t0 + 1) * 68 + i * 8 + kq] = e1[i];
    }
    __syncthreads();

    const float* encB = enc + (size_t)b * 64 * 256;
    for (int idx = tid; idx < 4096; idx += 256) {
        int k = idx >> 6, h4 = idx & 63;
        *(float4*)&WA[k * 260 + (h4 << 2)] = __ldg((const float4*)encB + idx);
    }
    __syncthreads();

    if (tid < 64) {
        float* er = &ES[tid * 68];
        float mx = -1e30f;
        for (int k = 0; k < 64; ++k) mx = fmaxf(mx, er[k]);
        float s = 0.f;
        for (int k = 0; k < 64; ++k) { float e = __expf(er[k] - mx); er[k] = e; s += e; }
        float inv = 1.f / s;
        for (int k = 0; k < 64; ++k) er[k] *= inv;
    }
    __syncthreads();

    const int tq2 = tid >> 4, hq = tid & 15;
    const int tb = tq2 * 4;
    float4 cacc[4][4];
#pragma unroll
    for (int dt = 0; dt < 4; ++dt)
#pragma unroll
        for (int jj = 0; jj < 4; ++jj) cacc[dt][jj] = make_float4(0.f, 0.f, 0.f, 0.f);

    for (int k = 0; k < 64; ++k) {
        float al[4];
#pragma unroll
        for (int dt = 0; dt < 4; ++dt) al[dt] = ES[(tb + dt) * 68 + k];
        float4 ev[4];
#pragma unroll
        for (int jj = 0; jj < 4; ++jj) ev[jj] = *(const float4*)&WA[k * 260 + hq * 16 + jj * 4];
#pragma unroll
        for (int dt = 0; dt < 4; ++dt)
#pragma unroll
            for (int jj = 0; jj < 4; ++jj) cacc[dt][jj] = ffma4(al[dt], ev[jj], cacc[dt][jj]);
    }
#pragma unroll
    for (int dt = 0; dt < 4; ++dt)
#pragma unroll
        for (int jj = 0; jj < 4; ++jj)
            *(float4*)&ctx[(size_t)(b * 64 + tb + dt) * 256 + hq * 16 + jj * 4] = cacc[dt][jj];
}

// ---------------- launch ----------------
extern "C" void kernel_launch(void* const* d_in, const int* in_sizes, int n_in,
                              void* d_out, int out_size)
{
    const int*   x     = (const int*)  d_in[0];
    const float* embed = (const float*)d_in[1];
    const float* w_ih0 = (const float*)d_in[2];
    const float* w_hh0 = (const float*)d_in[3];
    const float* b_ih0 = (const float*)d_in[4];
    const float* b_hh0 = (const float*)d_in[5];
    const float* w_ih1 = (const float*)d_in[6];
    const float* w_hh1 = (const float*)d_in[7];
    const float* b_ih1 = (const float*)d_in[8];
    const float* b_hh1 = (const float*)d_in[9];
    const float* W_a   = (const float*)d_in[10];
    const float* U_a   = (const float*)d_in[11];
    const float* v_a   = (const float*)d_in[12];
    const float* fc_W  = (const float*)d_in[13];
    const float* fc_b  = (const float*)d_in[14];

    float* out = (float*)d_out;                 // logits (B,T,V) then h_last (B,H)
    float* hlast = out + (size_t)BB * TT * VV;

    float *xp, *seq, *enc, *wa, *ua, *ctx;
    cudaGetSymbolAddress((void**)&xp,  g_xp);
    cudaGetSymbolAddress((void**)&seq, g_seq);
    cudaGetSymbolAddress((void**)&enc, g_enc);
    cudaGetSymbolAddress((void**)&wa,  g_Wa);
    cudaGetSymbolAddress((void**)&ua,  g_Ua);
    cudaGetSymbolAddress((void**)&ctx, g_ctx);

    cudaFuncSetAttribute(attn_k, cudaFuncAttributeMaxDynamicSharedMemorySize, AT_SMEM_BYTES);
    cudaFuncSetAttribute(scan_k, cudaFuncAttributeMaxDynamicSharedMemorySize, SCAN_SMEM_BYTES);

    const int M = BB * TT;  // 8192

    // 1. xp0 = embed[x] @ w_ih0^T + b_ih0    (gather fused)
    gemm_k<<<dim3(M / 128, G3H / 128), 256>>>(embed, HH, x, w_ih0, HH, b_ih0, xp, G3H, HH, 0);
    // 2. scan layer 0 (32 clusters x 4 CTAs, 512 threads)
    scan_k<<<128, 512, SCAN_SMEM_BYTES>>>(xp, w_hh0, b_hh0, seq, nullptr);
    // 3. xp1 = seq @ w_ih1^T + b_ih1
    gemm_k<<<dim3(M / 128, G3H / 128), 256>>>(seq, HH, nullptr, w_ih1, HH, b_ih1, xp, G3H, HH, 0);
    // 4. scan layer 1 -> enc, h_last
    scan_k<<<128, 512, SCAN_SMEM_BYTES>>>(xp, w_hh1, b_hh1, enc, hlast);
    // 5/6. attention projections
    gemm_k<<<dim3(M / 128, HH / 128), 256>>>(enc, HH, nullptr, W_a, HH, nullptr, wa, HH, HH, 0);
    gemm_k<<<dim3(M / 128, HH / 128), 256>>>(enc, HH, nullptr, U_a, HH, nullptr, ua, HH, HH, 0);
    // 7. attention -> ctx
    attn_k<<<BB, 256, AT_SMEM_BYTES>>>(wa, ua, enc, v_a, ctx);
    // 8/9. logits = enc @ fcW[:, :H]^T + b ; += ctx @ fcW[:, H:]^T
    gemm_k<<<dim3(M / 128, VV / 128), 256>>>(enc, HH, nullptr, fc_W, 2 * HH, fc_b, out, VV, HH, 0);
    gemm_k<<<dim3(M / 128, VV / 128), 256>>>(ctx, HH, nullptr, fc_W + HH, 2 * HH, nullptr, out, VV, HH, 1);
}

// round 15
// speedup vs baseline: 1.0531x; 1.0531x over previous
#include <cuda_runtime.h>
#include <cuda_bf16.h>
#include <cstdint>
#include <cstddef>

#define BB 128
#define TT 64
#define HH 256
#define VV 128
#define G3H 768
#define CATW 512

// ---------------- persistent scratch ----------------
__device__ float g_xp [BB*TT*G3H];     // input projections (both layers, reused)
__device__ float g_seq[BB*TT*HH];      // layer-0 output
__device__ float g_cat[BB*TT*CATW];    // [enc | ctx] concatenated (K=512 fc)
__device__ float g_Wa [BB*TT*HH];
__device__ float g_Ua [BB*TT*HH];

// ---------------- helpers ----------------
union F2U { float2 f; unsigned long long u; };

__device__ __forceinline__ float2 ffma2(float2 a, float2 b, float2 c) {
    F2U A, B, C, D; A.f = a; B.f = b; C.f = c;
    asm("fma.rn.f32x2 %0, %1, %2, %3;" : "=l"(D.u) : "l"(A.u), "l"(B.u), "l"(C.u));
    return D.f;
}

__device__ __forceinline__ float4 ffma4(float a, float4 b, float4 c) {
    float2 p = ffma2(make_float2(a, a), make_float2(b.x, b.y), make_float2(c.x, c.y));
    float2 q = ffma2(make_float2(a, a), make_float2(b.z, b.w), make_float2(c.z, c.w));
    return make_float4(p.x, p.y, q.x, q.y);
}

__device__ __forceinline__ float tanha(float x) {
    float y; asm("tanh.approx.f32 %0, %1;" : "=f"(y) : "f"(x)); return y;
}

__device__ __forceinline__ float sigm(float x) {
    return 1.f / (1.f + __expf(-x));
}

__device__ __forceinline__ float4 shfl4(float4 v, int src) {
    float4 r;
    r.x = __shfl_sync(0xffffffffu, v.x, src);
    r.y = __shfl_sync(0xffffffffu, v.y, src);
    r.z = __shfl_sync(0xffffffffu, v.z, src);
    r.w = __shfl_sync(0xffffffffu, v.w, src);
    return r;
}

__device__ __forceinline__ uint32_t smem_u32(const void* p) {
    uint32_t a;
    asm("{ .reg .u64 t; cvta.to.shared.u64 t, %1; cvt.u32.u64 %0, t; }" : "=r"(a) : "l"(p));
    return a;
}

#define MBARRIER_INIT(addr, cnt) \
    asm volatile("mbarrier.init.shared.b64 [%0], %1;" :: "r"(addr), "r"(cnt) : "memory")

#define MBARRIER_EXPECT_TX(addr, tx) \
    asm volatile("mbarrier.arrive.expect_tx.shared.b64 _, [%0], %1;" :: "r"(addr), "r"(tx) : "memory")

#define MBARRIER_WAIT_PARITY(addr, par) do {                                        \
    uint32_t _m = (addr); uint32_t _p = (par); uint32_t _done;                      \
    asm volatile("{\n\t.reg .pred p;\n\t"                                           \
        "mbarrier.try_wait.parity.acquire.cta.shared::cta.b64 p, [%1], %2;\n\t"     \
        "selp.b32 %0, 1, 0, p;\n\t}"                                                \
        : "=r"(_done) : "r"(_m), "r"(_p) : "memory");                               \
    if (!_done) {                                                                   \
        asm volatile("{\n\t.reg .pred P1;\n\t"                                      \
            "WL_%=:\n\t"                                                            \
            "mbarrier.try_wait.parity.acquire.cta.shared::cta.b64 P1, [%0], %1, 0x989680;\n\t" \
            "@P1 bra.uni WD_%=;\n\t"                                                \
            "bra.uni WL_%=;\n\t"                                                    \
            "WD_%=:\n\t}" :: "r"(_m), "r"(_p) : "memory");                          \
    }                                                                               \
} while (0)

#define ST_ASYNC_B32(raddr, uval, rmbar) \
    asm volatile("st.async.shared::cluster.mbarrier::complete_tx::bytes.b32 [%0], %1, [%2];" \
        :: "r"(raddr), "r"(uval), "r"(rmbar) : "memory")

#define MAPA_U32(dst, laddr, rank) \
    asm("mapa.shared::cluster.u32 %0, %1, %2;" : "=r"(dst) : "r"(laddr), "r"(rank))

#define CLUSTER_SYNC() do {                                              \
    asm volatile("barrier.cluster.arrive.aligned;" ::: "memory");        \
    asm volatile("barrier.cluster.wait.aligned;" ::: "memory");          \
} while (0)

// ---------------- GEMM: C[m,n] = sum_k A[m,k]*W[n,k] + bias ----------------
// BM=128 BN=128 BK=16, 256 threads, 8x8 per thread, f32x2 FMA.
// Double-buffered smem (one __syncthreads per k-tile), LDG prefetch ahead of
// compute. gather != null: A row m is A + gather[m]*lda.
__global__ void __launch_bounds__(256)
gemm_k(const float* __restrict__ A, int lda, const int* __restrict__ gather,
       const float* __restrict__ W, int ldw,
       const float* __restrict__ bias,
       float* __restrict__ C, int ldc, int K)
{
    __shared__ float As[2][16 * 132];
    __shared__ float Bs[2][16 * 132];

    const int tid = threadIdx.x;
    const int tx = tid & 15;           // n-octet
    const int ty = tid >> 4;           // m-octet
    const int mbase = blockIdx.x * 128;
    const int nbase = blockIdx.y * 128;

    const int ra = tid >> 2;           // rows ra and ra+64 (A and W)
    const int c4 = tid & 3;            // float4 column within 16-wide k-tile
    const int m0 = mbase + ra;
    const int m1 = mbase + ra + 64;
    const float* arow0 = A + (size_t)(gather ? gather[m0] : m0) * lda;
    const float* arow1 = A + (size_t)(gather ? gather[m1] : m1) * lda;
    const float* wrow0 = W + (size_t)(nbase + ra) * ldw;
    const float* wrow1 = W + (size_t)(nbase + ra + 64) * ldw;

    float4 acc[8][2];
#pragma unroll
    for (int i = 0; i < 8; ++i) {
        acc[i][0] = make_float4(0.f, 0.f, 0.f, 0.f);
        acc[i][1] = make_float4(0.f, 0.f, 0.f, 0.f);
    }

    const int ktiles = K >> 4;
    float4 Av0 = __ldg((const float4*)(arow0 + c4 * 4));
    float4 Av1 = __ldg((const float4*)(arow1 + c4 * 4));
    float4 Bv0 = __ldg((const float4*)(wrow0 + c4 * 4));
    float4 Bv1 = __ldg((const float4*)(wrow1 + c4 * 4));

    // stage tile 0 into buffer 0
    {
        float* as = As[0]; float* bs = Bs[0];
        as[(c4 * 4 + 0) * 132 + ra]      = Av0.x;
        as[(c4 * 4 + 1) * 132 + ra]      = Av0.y;
        as[(c4 * 4 + 2) * 132 + ra]      = Av0.z;
        as[(c4 * 4 + 3) * 132 + ra]      = Av0.w;
        as[(c4 * 4 + 0) * 132 + ra + 64] = Av1.x;
        as[(c4 * 4 + 1) * 132 + ra + 64] = Av1.y;
        as[(c4 * 4 + 2) * 132 + ra + 64] = Av1.z;
        as[(c4 * 4 + 3) * 132 + ra + 64] = Av1.w;
        bs[(c4 * 4 + 0) * 132 + ra]      = Bv0.x;
        bs[(c4 * 4 + 1) * 132 + ra]      = Bv0.y;
        bs[(c4 * 4 + 2) * 132 + ra]      = Bv0.z;
        bs[(c4 * 4 + 3) * 132 + ra]      = Bv0.w;
        bs[(c4 * 4 + 0) * 132 + ra + 64] = Bv1.x;
        bs[(c4 * 4 + 1) * 132 + ra + 64] = Bv1.y;
        bs[(c4 * 4 + 2) * 132 + ra + 64] = Bv1.z;
        bs[(c4 * 4 + 3) * 132 + ra + 64] = Bv1.w;
    }
    __syncthreads();

    for (int kt = 0; kt < ktiles; ++kt) {
        const int cur = kt & 1;
        const bool more = (kt + 1 < ktiles);
        if (more) {                       // prefetch next tile (consumed post-compute)
            Av0 = __ldg((const float4*)(arow0 + (kt + 1) * 16 + c4 * 4));
            Av1 = __ldg((const float4*)(arow1 + (kt + 1) * 16 + c4 * 4));
            Bv0 = __ldg((const float4*)(wrow0 + (kt + 1) * 16 + c4 * 4));
            Bv1 = __ldg((const float4*)(wrow1 + (kt + 1) * 16 + c4 * 4));
        }

        const float* as = As[cur];
        const float* bs = Bs[cur];
#pragma unroll
        for (int k = 0; k < 16; ++k) {
            float4 a0 = *(const float4*)&as[k * 132 + ty * 8];
            float4 a1 = *(const float4*)&as[k * 132 + ty * 8 + 4];
            float4 b0 = *(const float4*)&bs[k * 132 + tx * 8];
            float4 b1 = *(const float4*)&bs[k * 132 + tx * 8 + 4];
            acc[0][0] = ffma4(a0.x, b0, acc[0][0]); acc[0][1] = ffma4(a0.x, b1, acc[0][1]);
            acc[1][0] = ffma4(a0.y, b0, acc[1][0]); acc[1][1] = ffma4(a0.y, b1, acc[1][1]);
            acc[2][0] = ffma4(a0.z, b0, acc[2][0]); acc[2][1] = ffma4(a0.z, b1, acc[2][1]);
            acc[3][0] = ffma4(a0.w, b0, acc[3][0]); acc[3][1] = ffma4(a0.w, b1, acc[3][1]);
            acc[4][0] = ffma4(a1.x, b0, acc[4][0]); acc[4][1] = ffma4(a1.x, b1, acc[4][1]);
            acc[5][0] = ffma4(a1.y, b0, acc[5][0]); acc[5][1] = ffma4(a1.y, b1, acc[5][1]);
            acc[6][0] = ffma4(a1.z, b0, acc[6][0]); acc[6][1] = ffma4(a1.z, b1, acc[6][1]);
            acc[7][0] = ffma4(a1.w, b0, acc[7][0]); acc[7][1] = ffma4(a1.w, b1, acc[7][1]);
        }

        if (more) {                       // stage next tile into the other buffer
            float* asn = As[cur ^ 1]; float* bsn = Bs[cur ^ 1];
            asn[(c4 * 4 + 0) * 132 + ra]      = Av0.x;
            asn[(c4 * 4 + 1) * 132 + ra]      = Av0.y;
            asn[(c4 * 4 + 2) * 132 + ra]      = Av0.z;
            asn[(c4 * 4 + 3) * 132 + ra]      = Av0.w;
            asn[(c4 * 4 + 0) * 132 + ra + 64] = Av1.x;
            asn[(c4 * 4 + 1) * 132 + ra + 64] = Av1.y;
            asn[(c4 * 4 + 2) * 132 + ra + 64] = Av1.z;
            asn[(c4 * 4 + 3) * 132 + ra + 64] = Av1.w;
            bsn[(c4 * 4 + 0) * 132 + ra]      = Bv0.x;
            bsn[(c4 * 4 + 1) * 132 + ra]      = Bv0.y;
            bsn[(c4 * 4 + 2) * 132 + ra]      = Bv0.z;
            bsn[(c4 * 4 + 3) * 132 + ra]      = Bv0.w;
            bsn[(c4 * 4 + 0) * 132 + ra + 64] = Bv1.x;
            bsn[(c4 * 4 + 1) * 132 + ra + 64] = Bv1.y;
            bsn[(c4 * 4 + 2) * 132 + ra + 64] = Bv1.z;
            bsn[(c4 * 4 + 3) * 132 + ra + 64] = Bv1.w;
            __syncthreads();
        }
    }

    const int n0 = nbase + tx * 8;
    float4 bv0 = make_float4(0.f, 0.f, 0.f, 0.f);
    float4 bv1 = bv0;
    if (bias) { bv0 = *(const float4*)&bias[n0]; bv1 = *(const float4*)&bias[n0 + 4]; }
#pragma unroll
    for (int mi = 0; mi < 8; ++mi) {
        int m = mbase + ty * 8 + mi;
        float4* cp = (float4*)&C[(size_t)m * ldc + n0];
        float4 o0 = acc[mi][0], o1 = acc[mi][1];
        o0.x += bv0.x; o0.y += bv0.y; o0.z += bv0.z; o0.w += bv0.w;
        o1.x += bv1.x; o1.y += bv1.y; o1.z += bv1.z; o1.w += bv1.w;
        cp[0] = o0; cp[1] = o1;
    }
}

// ---------------- GRU scan: 32 clusters x 4 CTAs (R13-exact + ldseq) ----------------
// Thread (jg8 = tid>>3, kq = tid&7): j-pair {2*jg8, 2*jg8+1} x 4 batches x
// k-float4s {kq + 8i}. Weights read from smem EXACTLY ONCE per CTA per step.
// h preloaded to registers once per warp and distributed via shfl.idx.
// 8-way xor-shuffle reduction over kq; lane kq finalizes (j2=kq>>2, b=kq&3).
#define SCAN_WS_BYTES   (3 * 64 * 64 * 16)            // 196608
#define SCAN_HB_FLOATS  (2 * 4 * 264)                 // padded stride 264
#define SCAN_HB_BYTES   (SCAN_HB_FLOATS * 4)          // 8448
#define SCAN_SMEM_BYTES (SCAN_WS_BYTES + SCAN_HB_BYTES + 16)

__global__ void __launch_bounds__(256, 1) __cluster_dims__(4, 1, 1)
scan_k(const float* __restrict__ xp, const float* __restrict__ w_hh,
       const float* __restrict__ b_hh, float* __restrict__ seq, int ldseq,
       float* __restrict__ hlast)
{
    extern __shared__ __align__(16) unsigned char sm_raw[];
    float4* ws = (float4*)sm_raw;                               // [3][64 j][64 f4]
    float*  hb = (float*)(sm_raw + SCAN_WS_BYTES);              // [2][4][264]
    unsigned long long* mbar =
        (unsigned long long*)(sm_raw + SCAN_WS_BYTES + SCAN_HB_BYTES);

    const int g   = blockIdx.x >> 2;
    const int tid = threadIdx.x;
    const int jg8 = tid >> 3;                 // 0..31  j-pair group
    const int kq  = tid & 7;                  // 0..7   k-slice
    const int jl0 = jg8 * 2;
    uint32_t rank;
    asm("mov.u32 %0, %%cluster_ctarank;" : "=r"(rank));
    const int b0 = g * 4;

    // warp-local h ownership: lane l holds h[b=l&3][f4=(l>>2)+8r]
    const int lane   = tid & 31;
    const int b_own  = lane & 3;
    const int blk    = lane >> 2;             // 0..7

    // output assignment: lane kq finalizes (j2 = kq>>2, b = kq&3)
    const int j2o   = kq >> 2;
    const int b_out = kq & 3;
    const int jlo   = jl0 + j2o;              // local j of output
    const int jgo   = (int)rank * 64 + jlo;   // global hidden index

    // ---- prologue: copy w_hh slice (row-major, identity in f4) ----
    for (int idx = tid; idx < 3 * 64 * 64; idx += 256) {
        int gg = idx >> 12;
        int jl = (idx >> 6) & 63;
        int f4 = idx & 63;
        ws[idx] = __ldg((const float4*)(w_hh +
                    (size_t)(gg * 256 + (int)rank * 64 + jl) * 256) + f4);
    }

    const float bh0 = b_hh[jgo], bh1 = b_hh[256 + jgo], bh2 = b_hh[512 + jgo];

    const uint32_t mb0 = smem_u32(&mbar[0]);
    const uint32_t myh = smem_u32(&hb[(size_t)b_out * 264 + jgo]);  // parity-0 slot
    uint32_t rh[4], rm[4];
#pragma unroll
    for (int r = 0; r < 4; ++r) { MAPA_U32(rh[r], myh, r); MAPA_U32(rm[r], mb0, r); }

    if (tid == 0) { MBARRIER_INIT(mb0, 1); MBARRIER_INIT(mb0 + 8, 1); }
    __syncthreads();
    CLUSTER_SYNC();                       // all mbars + ws live before any st.async
    if (tid == 0) {
        MBARRIER_EXPECT_TX(mb0, 4096);
        MBARRIER_EXPECT_TX(mb0 + 8, 4096);
    }

    const float* xpb = xp + (size_t)(b0 + b_out) * TT * G3H;
    const float4* wp = ws + (size_t)jl0 * 64 + kq;   // + g*4096 + j2*64 + 8i
    float hprev = 0.f;
    int ph0 = 0, ph1 = 0;

    for (int t = 0; t < TT; ++t) {
        // prefetch xp for this (b_out, t) — hidden under wait + matvec
        const float* xr_p = xpb + (size_t)t * G3H;
        const float xr = __ldcg(xr_p + jgo);
        const float xz = __ldcg(xr_p + 256 + jgo);
        const float xn = __ldcg(xr_p + 512 + jgo);

        float hr, hz, hn;
        if (t == 0) {
            hr = bh0; hz = bh1; hn = bh2;           // h == 0
        } else {
            const int ip = (t - 1) & 1;
            if (ip == 0) { MBARRIER_WAIT_PARITY(mb0, ph0);     ph0 ^= 1; }
            else         { MBARRIER_WAIT_PARITY(mb0 + 8, ph1); ph1 ^= 1; }
            if (tid == 0) MBARRIER_EXPECT_TX(mb0 + 8 * ip, 4096);  // re-arm

            // preload h to registers (one read of h per warp total)
            const float4* hrow = (const float4*)(hb + (size_t)ip * 1056 +
                                                 (size_t)b_own * 264);
            float4 hreg[8];
#pragma unroll
            for (int r = 0; r < 8; ++r) hreg[r] = hrow[blk + 8 * r];

            float2 acc[2][4][3];
#pragma unroll
            for (int j2 = 0; j2 < 2; ++j2)
#pragma unroll
                for (int b = 0; b < 4; ++b)
#pragma unroll
                    for (int gg = 0; gg < 3; ++gg)
                        acc[j2][b][gg] = make_float2(0.f, 0.f);

#pragma unroll
            for (int i = 0; i < 8; ++i) {
                float4 wv[2][3];
#pragma unroll
                for (int j2 = 0; j2 < 2; ++j2) {
#pragma unroll
                    for (int gg = 0; gg < 3; ++gg)
                        wv[j2][gg] = wp[gg * 4096 + j2 * 64 + 8 * i];
                }
#pragma unroll
                for (int b = 0; b < 4; ++b) {
                    float4 hv = shfl4(hreg[i], (kq << 2) | b);
                    float2 hxy = make_float2(hv.x, hv.y);
                    float2 hzw = make_float2(hv.z, hv.w);
#pragma unroll
                    for (int j2 = 0; j2 < 2; ++j2) {
#pragma unroll
                        for (int gg = 0; gg < 3; ++gg) {
                            acc[j2][b][gg] = ffma2(make_float2(wv[j2][gg].x, wv[j2][gg].y),
                                                   hxy, acc[j2][b][gg]);
                            acc[j2][b][gg] = ffma2(make_float2(wv[j2][gg].z, wv[j2][gg].w),
                                                   hzw, acc[j2][b][gg]);
                        }
                    }
                }
            }

            // horizontal + 8-way xor reduction over kq lanes
            float s[2][4][3];
#pragma unroll
            for (int j2 = 0; j2 < 2; ++j2)
#pragma unroll
                for (int b = 0; b < 4; ++b)
#pragma unroll
                    for (int gg = 0; gg < 3; ++gg) {
                        float v = acc[j2][b][gg].x + acc[j2][b][gg].y;
                        v += __shfl_xor_sync(0xffffffffu, v, 1);
                        v += __shfl_xor_sync(0xffffffffu, v, 2);
                        v += __shfl_xor_sync(0xffffffffu, v, 4);
                        s[j2][b][gg] = v;
                    }

            hr = bh0; hz = bh1; hn = bh2;
#pragma unroll
            for (int j2 = 0; j2 < 2; ++j2)
#pragma unroll
                for (int b = 0; b < 4; ++b)
                    if (kq == ((j2 << 2) | b)) {
                        hr += s[j2][b][0];
                        hz += s[j2][b][1];
                        hn += s[j2][b][2];
                    }
        }

        const float r = sigm(xr + hr);
        const float z = sigm(xz + hz);
        const float n = tanhf(xn + r * hn);
        const float hnew = (1.f - z) * n + z * hprev;
        hprev = hnew;

        __stcg(&seq[((size_t)(b0 + b_out) * TT + t) * ldseq + jgo], hnew);
        if (hlast != nullptr && t == TT - 1)
            __stcg(&hlast[(size_t)(b0 + b_out) * HH + jgo], hnew);

        // broadcast my h value to all 4 CTAs' buffer[t&1]
        const uint32_t po = (uint32_t)(t & 1) * 4224u;      // 1056 floats
        const uint32_t uval = __float_as_uint(hnew);
#pragma unroll
        for (int r2 = 0; r2 < 4; ++r2)
            ST_ASYNC_B32(rh[r2] + po, uval, rm[r2] + (uint32_t)(t & 1) * 8u);
    }

    // drain: consume the final phase so no st.async targets our smem after exit
    MBARRIER_WAIT_PARITY(mb0 + 8, ph1);
    CLUSTER_SYNC();
}

// ---------------- attention (CTA per batch); enc from cat, ctx into cat ----------------
#define AT_SMEM_FLOATS (2 * 64 * 260 + 64 * 68 + 256)
#define AT_SMEM_BYTES  (AT_SMEM_FLOATS * 4)

__global__ void __launch_bounds__(256, 1)
attn_k(const float* __restrict__ Wa, const float* __restrict__ Ua,
       float* __restrict__ cat, const float* __restrict__ va)
{
    extern __shared__ float sm[];
    float* WA = sm;
    float* UA = sm + 64 * 260;
    float* ES = sm + 2 * 64 * 260;
    float* VS = ES + 64 * 68;

    const int b = blockIdx.x;
    const int tid = threadIdx.x;
    const float* waB = Wa + (size_t)b * 64 * 256;
    const float* uaB = Ua + (size_t)b * 64 * 256;

    for (int idx = tid; idx < 4096; idx += 256) {
        int k = idx >> 6, h4 = idx & 63;
        float4 w4 = __ldg((const float4*)waB + idx);
        *(float4*)&WA[k * 260 + ((h4 ^ (k & 7)) << 2)] = w4;   // xor swizzle
        float4 u4 = __ldg((const float4*)uaB + idx);
        *(float4*)&UA[k * 260 + (h4 << 2)] = u4;
    }
    if (tid < 64) *(float4*)&VS[tid * 4] = __ldg((const float4*)va + tid);
    __syncthreads();

    const int tq = tid >> 3, kq = tid & 7;
    const int t0 = tq * 2;
    float e0[8], e1[8];
#pragma unroll
    for (int i = 0; i < 8; ++i) { e0[i] = 0.f; e1[i] = 0.f; }

    for (int h4 = 0; h4 < 64; ++h4) {
        float4 v4 = *(const float4*)&VS[h4 * 4];
        float4 uA = *(const float4*)&UA[t0 * 260 + h4 * 4];
        float4 uB = *(const float4*)&UA[(t0 + 1) * 260 + h4 * 4];
#pragma unroll
        for (int i = 0; i < 8; ++i) {
            int k = i * 8 + kq;
            float4 w4 = *(const float4*)&WA[k * 260 + ((h4 ^ kq) << 2)];
            e0[i] += tanha(w4.x + uA.x) * v4.x + tanha(w4.y + uA.y) * v4.y
                   + tanha(w4.z + uA.z) * v4.z + tanha(w4.w + uA.w) * v4.w;
            e1[i] += tanha(w4.x + uB.x) * v4.x + tanha(w4.y + uB.y) * v4.y
                   + tanha(w4.z + uB.z) * v4.z + tanha(w4.w + uB.w) * v4.w;
        }
    }
#pragma unroll
    for (int i = 0; i < 8; ++i) {
        ES[t0 * 68 + i * 8 + kq] = e0[i];
        ES[(t0 + 1) * 68 + i * 8 + kq] = e1[i];
    }
    __syncthreads();

    // reload enc (cat[:, 0:256]) into WA (plain layout, stride 260)
    for (int idx = tid; idx < 4096; idx += 256) {
        int k = idx >> 6, h4 = idx & 63;
        float4 e4 = __ldg((const float4*)(cat + (size_t)(b * 64 + k) * CATW) + h4);
        *(float4*)&WA[k * 260 + (h4 << 2)] = e4;
    }
    __syncthreads();

    if (tid < 64) {
        float* er = &ES[tid * 68];
        float mx = -1e30f;
        for (int k = 0; k < 64; ++k) mx = fmaxf(mx, er[k]);
        float s = 0.f;
        for (int k = 0; k < 64; ++k) { float e = __expf(er[k] - mx); er[k] = e; s += e; }
        float inv = 1.f / s;
        for (int k = 0; k < 64; ++k) er[k] *= inv;
    }
    __syncthreads();

    const int tq2 = tid >> 4, hq = tid & 15;
    const int tb = tq2 * 4;
    float4 cacc[4][4];
#pragma unroll
    for (int dt = 0; dt < 4; ++dt)
#pragma unroll
        for (int jj = 0; jj < 4; ++jj) cacc[dt][jj] = make_float4(0.f, 0.f, 0.f, 0.f);

    for (int k = 0; k < 64; ++k) {
        float al[4];
#pragma unroll
        for (int dt = 0; dt < 4; ++dt) al[dt] = ES[(tb + dt) * 68 + k];
        float4 ev[4];
#pragma unroll
        for (int jj = 0; jj < 4; ++jj) ev[jj] = *(const float4*)&WA[k * 260 + hq * 16 + jj * 4];
#pragma unroll
        for (int dt = 0; dt < 4; ++dt)
#pragma unroll
            for (int jj = 0; jj < 4; ++jj) cacc[dt][jj] = ffma4(al[dt], ev[jj], cacc[dt][jj]);
    }
    // ctx -> cat[:, 256:512]
#pragma unroll
    for (int dt = 0; dt < 4; ++dt)
#pragma unroll
        for (int jj = 0; jj < 4; ++jj)
            *(float4*)&cat[(size_t)(b * 64 + tb + dt) * CATW + 256 + hq * 16 + jj * 4]
                = cacc[dt][jj];
}

// ---------------- launch ----------------
extern "C" void kernel_launch(void* const* d_in, const int* in_sizes, int n_in,
                              void* d_out, int out_size)
{
    const int*   x     = (const int*)  d_in[0];
    const float* embed = (const float*)d_in[1];
    const float* w_ih0 = (const float*)d_in[2];
    const float* w_hh0 = (const float*)d_in[3];
    const float* b_ih0 = (const float*)d_in[4];
    const float* b_hh0 = (const float*)d_in[5];
    const float* w_ih1 = (const float*)d_in[6];
    const float* w_hh1 = (const float*)d_in[7];
    const float* b_ih1 = (const float*)d_in[8];
    const float* b_hh1 = (const float*)d_in[9];
    const float* W_a   = (const float*)d_in[10];
    const float* U_a   = (const float*)d_in[11];
    const float* v_a   = (const float*)d_in[12];
    const float* fc_W  = (const float*)d_in[13];
    const float* fc_b  = (const float*)d_in[14];

    float* out = (float*)d_out;                 // logits (B,T,V) then h_last (B,H)
    float* hlast = out + (size_t)BB * TT * VV;

    float *xp, *seq, *cat, *wa, *ua;
    cudaGetSymbolAddress((void**)&xp,  g_xp);
    cudaGetSymbolAddress((void**)&seq, g_seq);
    cudaGetSymbolAddress((void**)&cat, g_cat);
    cudaGetSymbolAddress((void**)&wa,  g_Wa);
    cudaGetSymbolAddress((void**)&ua,  g_Ua);

    cudaFuncSetAttribute(attn_k, cudaFuncAttributeMaxDynamicSharedMemorySize, AT_SMEM_BYTES);
    cudaFuncSetAttribute(scan_k, cudaFuncAttributeMaxDynamicSharedMemorySize, SCAN_SMEM_BYTES);

    const int M = BB * TT;  // 8192

    // 1. xp0 = embed[x] @ w_ih0^T + b_ih0    (gather fused)
    gemm_k<<<dim3(M / 128, G3H / 128), 256>>>(embed, HH, x, w_ih0, HH, b_ih0, xp, G3H, HH);
    // 2. scan layer 0 -> seq (stride 256)
    scan_k<<<128, 256, SCAN_SMEM_BYTES>>>(xp, w_hh0, b_hh0, seq, HH, nullptr);
    // 3. xp1 = seq @ w_ih1^T + b_ih1
    gemm_k<<<dim3(M / 128, G3H / 128), 256>>>(seq, HH, nullptr, w_ih1, HH, b_ih1, xp, G3H, HH);
    // 4. scan layer 1 -> cat[:, 0:256] (stride 512), h_last
    scan_k<<<128, 256, SCAN_SMEM_BYTES>>>(xp, w_hh1, b_hh1, cat, CATW, hlast);
    // 5/6. attention projections (A = enc inside cat, lda=512)
    gemm_k<<<dim3(M / 128, HH / 128), 256>>>(cat, CATW, nullptr, W_a, HH, nullptr, wa, HH, HH);
    gemm_k<<<dim3(M / 128, HH / 128), 256>>>(cat, CATW, nullptr, U_a, HH, nullptr, ua, HH, HH);
    // 7. attention -> ctx into cat[:, 256:512]
    attn_k<<<BB, 256, AT_SMEM_BYTES>>>(wa, ua, cat, v_a);
    // 8. logits = cat @ fc_W^T + fc_b   (single K=512 pass)
    gemm_k<<<dim3(M / 128, VV / 128), 256>>>(cat, CATW, nullptr, fc_W, 2 * HH, fc_b, out, VV, 2 * HH);
}

// round 16
// speedup vs baseline: 1.1178x; 1.0614x over previous
#include <cuda_runtime.h>
#include <cuda_bf16.h>
#include <cstdint>
#include <cstddef>

#define BB 128
#define TT 64
#define HH 256
#define VV 128
#define G3H 768
#define CATW 512

// ---------------- persistent scratch ----------------
__device__ float g_xp [BB*TT*G3H];     // input projections (both layers, reused)
__device__ float g_seq[BB*TT*HH];      // layer-0 output
__device__ float g_cat[BB*TT*CATW];    // [enc | ctx] concatenated (K=512 fc)
__device__ float g_Wa [BB*TT*HH];
__device__ float g_Ua [BB*TT*HH];

// ---------------- helpers ----------------
union F2U { float2 f; unsigned long long u; };

__device__ __forceinline__ float2 ffma2(float2 a, float2 b, float2 c) {
    F2U A, B, C, D; A.f = a; B.f = b; C.f = c;
    asm("fma.rn.f32x2 %0, %1, %2, %3;" : "=l"(D.u) : "l"(A.u), "l"(B.u), "l"(C.u));
    return D.f;
}

__device__ __forceinline__ float4 ffma4(float a, float4 b, float4 c) {
    float2 p = ffma2(make_float2(a, a), make_float2(b.x, b.y), make_float2(c.x, c.y));
    float2 q = ffma2(make_float2(a, a), make_float2(b.z, b.w), make_float2(c.z, c.w));
    return make_float4(p.x, p.y, q.x, q.y);
}

__device__ __forceinline__ float tanha(float x) {
    float y; asm("tanh.approx.f32 %0, %1;" : "=f"(y) : "f"(x)); return y;
}

__device__ __forceinline__ float sigm(float x) {
    return 1.f / (1.f + __expf(-x));
}

__device__ __forceinline__ float4 shfl4(float4 v, int src) {
    float4 r;
    r.x = __shfl_sync(0xffffffffu, v.x, src);
    r.y = __shfl_sync(0xffffffffu, v.y, src);
    r.z = __shfl_sync(0xffffffffu, v.z, src);
    r.w = __shfl_sync(0xffffffffu, v.w, src);
    return r;
}

__device__ __forceinline__ uint32_t smem_u32(const void* p) {
    uint32_t a;
    asm("{ .reg .u64 t; cvta.to.shared.u64 t, %1; cvt.u32.u64 %0, t; }" : "=r"(a) : "l"(p));
    return a;
}

#define MBARRIER_INIT(addr, cnt) \
    asm volatile("mbarrier.init.shared.b64 [%0], %1;" :: "r"(addr), "r"(cnt) : "memory")

#define MBARRIER_EXPECT_TX(addr, tx) \
    asm volatile("mbarrier.arrive.expect_tx.shared.b64 _, [%0], %1;" :: "r"(addr), "r"(tx) : "memory")

#define MBARRIER_WAIT_PARITY(addr, par) do {                                        \
    uint32_t _m = (addr); uint32_t _p = (par); uint32_t _done;                      \
    asm volatile("{\n\t.reg .pred p;\n\t"                                           \
        "mbarrier.try_wait.parity.acquire.cta.shared::cta.b64 p, [%1], %2;\n\t"     \
        "selp.b32 %0, 1, 0, p;\n\t}"                                                \
        : "=r"(_done) : "r"(_m), "r"(_p) : "memory");                               \
    if (!_done) {                                                                   \
        asm volatile("{\n\t.reg .pred P1;\n\t"                                      \
            "WL_%=:\n\t"                                                            \
            "mbarrier.try_wait.parity.acquire.cta.shared::cta.b64 P1, [%0], %1, 0x989680;\n\t" \
            "@P1 bra.uni WD_%=;\n\t"                                                \
            "bra.uni WL_%=;\n\t"                                                    \
            "WD_%=:\n\t}" :: "r"(_m), "r"(_p) : "memory");                          \
    }                                                                               \
} while (0)

#define ST_ASYNC_B32(raddr, uval, rmbar) \
    asm volatile("st.async.shared::cluster.mbarrier::complete_tx::bytes.b32 [%0], %1, [%2];" \
        :: "r"(raddr), "r"(uval), "r"(rmbar) : "memory")

#define MAPA_U32(dst, laddr, rank) \
    asm("mapa.shared::cluster.u32 %0, %1, %2;" : "=r"(dst) : "r"(laddr), "r"(rank))

#define CLUSTER_SYNC() do {                                              \
    asm volatile("barrier.cluster.arrive.aligned;" ::: "memory");        \
    asm volatile("barrier.cluster.wait.aligned;" ::: "memory");          \
} while (0)

// ---------------- GEMM body: C[m,n] = sum_k A[m,k]*W[n,k] + bias ----------------
// BM x 128 x 16 tiles, 256 threads, (BM/16) x 8 per thread, f32x2 FMA,
// register-staged prefetch, single-buffered smem (R13-proven mainloop).
// gather != null: A row m is A + gather[m]*lda.
template <int BM>
__device__ __forceinline__ void gemm_body(
    const float* __restrict__ A, int lda, const int* __restrict__ gather,
    const float* __restrict__ W, int ldw,
    const float* __restrict__ bias,
    float* __restrict__ C, int ldc, int K)
{
    constexpr int AP = BM + 4;
    constexpr int MR = BM / 16;          // 8 (BM=128) or 4 (BM=64)
    __shared__ float As[16 * AP];
    __shared__ float Bs[16 * 132];

    const int tid = threadIdx.x;
    const int tx = tid & 15;             // n-octet
    const int ty = tid >> 4;             // m-group
    const int mbase = blockIdx.x * BM;
    const int nbase = blockIdx.y * 128;

    const int ra = tid >> 2;             // 0..63
    const int c4 = tid & 3;              // float4 column within 16-wide k-tile

    const int m0 = mbase + (BM == 128 ? ra : (tid >> 2));
    const float* arow0 = A + (size_t)(gather ? gather[m0] : m0) * lda;
    const float* arow1 = nullptr;
    if (BM == 128) {
        const int m1 = mbase + ra + 64;
        arow1 = A + (size_t)(gather ? gather[m1] : m1) * lda;
    }
    const float* wrow0 = W + (size_t)(nbase + ra) * ldw;
    const float* wrow1 = W + (size_t)(nbase + ra + 64) * ldw;

    float4 acc[MR][2];
#pragma unroll
    for (int i = 0; i < MR; ++i) {
        acc[i][0] = make_float4(0.f, 0.f, 0.f, 0.f);
        acc[i][1] = make_float4(0.f, 0.f, 0.f, 0.f);
    }

    const int ktiles = K >> 4;
    float4 Av0 = __ldg((const float4*)(arow0 + c4 * 4));
    float4 Av1 = make_float4(0.f, 0.f, 0.f, 0.f);
    if (BM == 128) Av1 = __ldg((const float4*)(arow1 + c4 * 4));
    float4 Bv0 = __ldg((const float4*)(wrow0 + c4 * 4));
    float4 Bv1 = __ldg((const float4*)(wrow1 + c4 * 4));

    for (int kt = 0; kt < ktiles; ++kt) {
        // regs -> smem (transposed)
        As[(c4 * 4 + 0) * AP + ra] = Av0.x;
        As[(c4 * 4 + 1) * AP + ra] = Av0.y;
        As[(c4 * 4 + 2) * AP + ra] = Av0.z;
        As[(c4 * 4 + 3) * AP + ra] = Av0.w;
        if (BM == 128) {
            As[(c4 * 4 + 0) * AP + ra + 64] = Av1.x;
            As[(c4 * 4 + 1) * AP + ra + 64] = Av1.y;
            As[(c4 * 4 + 2) * AP + ra + 64] = Av1.z;
            As[(c4 * 4 + 3) * AP + ra + 64] = Av1.w;
        }
        Bs[(c4 * 4 + 0) * 132 + ra]      = Bv0.x;
        Bs[(c4 * 4 + 1) * 132 + ra]      = Bv0.y;
        Bs[(c4 * 4 + 2) * 132 + ra]      = Bv0.z;
        Bs[(c4 * 4 + 3) * 132 + ra]      = Bv0.w;
        Bs[(c4 * 4 + 0) * 132 + ra + 64] = Bv1.x;
        Bs[(c4 * 4 + 1) * 132 + ra + 64] = Bv1.y;
        Bs[(c4 * 4 + 2) * 132 + ra + 64] = Bv1.z;
        Bs[(c4 * 4 + 3) * 132 + ra + 64] = Bv1.w;
        __syncthreads();

        if (kt + 1 < ktiles) {            // prefetch next tile while computing
            Av0 = __ldg((const float4*)(arow0 + (kt + 1) * 16 + c4 * 4));
            if (BM == 128)
                Av1 = __ldg((const float4*)(arow1 + (kt + 1) * 16 + c4 * 4));
            Bv0 = __ldg((const float4*)(wrow0 + (kt + 1) * 16 + c4 * 4));
            Bv1 = __ldg((const float4*)(wrow1 + (kt + 1) * 16 + c4 * 4));
        }

#pragma unroll
        for (int k = 0; k < 16; ++k) {
            float4 b0 = *(const float4*)&Bs[k * 132 + tx * 8];
            float4 b1 = *(const float4*)&Bs[k * 132 + tx * 8 + 4];
            if (BM == 128) {
                float4 a0 = *(const float4*)&As[k * AP + ty * 8];
                float4 a1 = *(const float4*)&As[k * AP + ty * 8 + 4];
                acc[0][0] = ffma4(a0.x, b0, acc[0][0]); acc[0][1] = ffma4(a0.x, b1, acc[0][1]);
                acc[1][0] = ffma4(a0.y, b0, acc[1][0]); acc[1][1] = ffma4(a0.y, b1, acc[1][1]);
                acc[2][0] = ffma4(a0.z, b0, acc[2][0]); acc[2][1] = ffma4(a0.z, b1, acc[2][1]);
                acc[3][0] = ffma4(a0.w, b0, acc[3][0]); acc[3][1] = ffma4(a0.w, b1, acc[3][1]);
                acc[4][0] = ffma4(a1.x, b0, acc[4][0]); acc[4][1] = ffma4(a1.x, b1, acc[4][1]);
                acc[5][0] = ffma4(a1.y, b0, acc[5][0]); acc[5][1] = ffma4(a1.y, b1, acc[5][1]);
                acc[6][0] = ffma4(a1.z, b0, acc[6][0]); acc[6][1] = ffma4(a1.z, b1, acc[6][1]);
                acc[7][0] = ffma4(a1.w, b0, acc[7][0]); acc[7][1] = ffma4(a1.w, b1, acc[7][1]);
            } else {
                float4 a0 = *(const float4*)&As[k * AP + ty * 4];
                acc[0][0] = ffma4(a0.x, b0, acc[0][0]); acc[0][1] = ffma4(a0.x, b1, acc[0][1]);
                acc[1][0] = ffma4(a0.y, b0, acc[1][0]); acc[1][1] = ffma4(a0.y, b1, acc[1][1]);
                acc[2][0] = ffma4(a0.z, b0, acc[2][0]); acc[2][1] = ffma4(a0.z, b1, acc[2][1]);
                acc[3][0] = ffma4(a0.w, b0, acc[3][0]); acc[3][1] = ffma4(a0.w, b1, acc[3][1]);
            }
        }
        __syncthreads();
    }

    const int n0 = nbase + tx * 8;
    float4 bv0 = make_float4(0.f, 0.f, 0.f, 0.f);
    float4 bv1 = bv0;
    if (bias) { bv0 = *(const float4*)&bias[n0]; bv1 = *(const float4*)&bias[n0 + 4]; }
#pragma unroll
    for (int mi = 0; mi < MR; ++mi) {
        int m = mbase + ty * MR + mi;
        float4* cp = (float4*)&C[(size_t)m * ldc + n0];
        float4 o0 = acc[mi][0], o1 = acc[mi][1];
        o0.x += bv0.x; o0.y += bv0.y; o0.z += bv0.z; o0.w += bv0.w;
        o1.x += bv1.x; o1.y += bv1.y; o1.z += bv1.z; o1.w += bv1.w;
        cp[0] = o0; cp[1] = o1;
    }
}

__global__ void __launch_bounds__(256)
gemm128_k(const float* __restrict__ A, int lda, const int* __restrict__ gather,
          const float* __restrict__ W, int ldw, const float* __restrict__ bias,
          float* __restrict__ C, int ldc, int K)
{
    gemm_body<128>(A, lda, gather, W, ldw, bias, C, ldc, K);
}

__global__ void __launch_bounds__(256)
gemm64_k(const float* __restrict__ A, int lda, const int* __restrict__ gather,
         const float* __restrict__ W, int ldw, const float* __restrict__ bias,
         float* __restrict__ C, int ldc, int K)
{
    gemm_body<64>(A, lda, gather, W, ldw, bias, C, ldc, K);
}

// Wa and Ua projections in one launch: blockIdx.z selects (W0->C0) or (W1->C1).
__global__ void __launch_bounds__(256)
gemm_dual_k(const float* __restrict__ A, int lda,
            const float* __restrict__ W0, const float* __restrict__ W1,
            float* __restrict__ C0, float* __restrict__ C1, int K)
{
    const float* W = blockIdx.z ? W1 : W0;
    float*       C = blockIdx.z ? C1 : C0;
    gemm_body<128>(A, lda, nullptr, W, HH, nullptr, C, HH, K);
}

// ---------------- GRU scan: 32 clusters x 4 CTAs (R13-exact + ldseq) ----------------
// Thread (jg8 = tid>>3, kq = tid&7): j-pair {2*jg8, 2*jg8+1} x 4 batches x
// k-float4s {kq + 8i}. Weights read from smem EXACTLY ONCE per CTA per step.
// h preloaded to registers once per warp and distributed via shfl.idx.
// 8-way xor-shuffle reduction over kq; lane kq finalizes (j2=kq>>2, b=kq&3).
#define SCAN_WS_BYTES   (3 * 64 * 64 * 16)            // 196608
#define SCAN_HB_FLOATS  (2 * 4 * 264)                 // padded stride 264
#define SCAN_HB_BYTES   (SCAN_HB_FLOATS * 4)          // 8448
#define SCAN_SMEM_BYTES (SCAN_WS_BYTES + SCAN_HB_BYTES + 16)

__global__ void __launch_bounds__(256, 1) __cluster_dims__(4, 1, 1)
scan_k(const float* __restrict__ xp, const float* __restrict__ w_hh,
       const float* __restrict__ b_hh, float* __restrict__ seq, int ldseq,
       float* __restrict__ hlast)
{
    extern __shared__ __align__(16) unsigned char sm_raw[];
    float4* ws = (float4*)sm_raw;                               // [3][64 j][64 f4]
    float*  hb = (float*)(sm_raw + SCAN_WS_BYTES);              // [2][4][264]
    unsigned long long* mbar =
        (unsigned long long*)(sm_raw + SCAN_WS_BYTES + SCAN_HB_BYTES);

    const int g   = blockIdx.x >> 2;
    const int tid = threadIdx.x;
    const int jg8 = tid >> 3;                 // 0..31  j-pair group
    const int kq  = tid & 7;                  // 0..7   k-slice
    const int jl0 = jg8 * 2;
    uint32_t rank;
    asm("mov.u32 %0, %%cluster_ctarank;" : "=r"(rank));
    const int b0 = g * 4;

    // warp-local h ownership: lane l holds h[b=l&3][f4=(l>>2)+8r]
    const int lane   = tid & 31;
    const int b_own  = lane & 3;
    const int blk    = lane >> 2;             // 0..7

    // output assignment: lane kq finalizes (j2 = kq>>2, b = kq&3)
    const int j2o   = kq >> 2;
    const int b_out = kq & 3;
    const int jlo   = jl0 + j2o;              // local j of output
    const int jgo   = (int)rank * 64 + jlo;   // global hidden index

    // ---- prologue: copy w_hh slice (row-major, identity in f4) ----
    for (int idx = tid; idx < 3 * 64 * 64; idx += 256) {
        int gg = idx >> 12;
        int jl = (idx >> 6) & 63;
        int f4 = idx & 63;
        ws[idx] = __ldg((const float4*)(w_hh +
                    (size_t)(gg * 256 + (int)rank * 64 + jl) * 256) + f4);
    }

    const float bh0 = b_hh[jgo], bh1 = b_hh[256 + jgo], bh2 = b_hh[512 + jgo];

    const uint32_t mb0 = smem_u32(&mbar[0]);
    const uint32_t myh = smem_u32(&hb[(size_t)b_out * 264 + jgo]);  // parity-0 slot
    uint32_t rh[4], rm[4];
#pragma unroll
    for (int r = 0; r < 4; ++r) { MAPA_U32(rh[r], myh, r); MAPA_U32(rm[r], mb0, r); }

    if (tid == 0) { MBARRIER_INIT(mb0, 1); MBARRIER_INIT(mb0 + 8, 1); }
    __syncthreads();
    CLUSTER_SYNC();                       // all mbars + ws live before any st.async
    if (tid == 0) {
        MBARRIER_EXPECT_TX(mb0, 4096);
        MBARRIER_EXPECT_TX(mb0 + 8, 4096);
    }

    const float* xpb = xp + (size_t)(b0 + b_out) * TT * G3H;
    const float4* wp = ws + (size_t)jl0 * 64 + kq;   // + g*4096 + j2*64 + 8i
    float hprev = 0.f;
    int ph0 = 0, ph1 = 0;

    for (int t = 0; t < TT; ++t) {
        // prefetch xp for this (b_out, t) — hidden under wait + matvec
        const float* xr_p = xpb + (size_t)t * G3H;
        const float xr = __ldcg(xr_p + jgo);
        const float xz = __ldcg(xr_p + 256 + jgo);
        const float xn = __ldcg(xr_p + 512 + jgo);

        float hr, hz, hn;
        if (t == 0) {
            hr = bh0; hz = bh1; hn = bh2;           // h == 0
        } else {
            const int ip = (t - 1) & 1;
            if (ip == 0) { MBARRIER_WAIT_PARITY(mb0, ph0);     ph0 ^= 1; }
            else         { MBARRIER_WAIT_PARITY(mb0 + 8, ph1); ph1 ^= 1; }
            if (tid == 0) MBARRIER_EXPECT_TX(mb0 + 8 * ip, 4096);  // re-arm

            // preload h to registers (one read of h per warp total)
            const float4* hrow = (const float4*)(hb + (size_t)ip * 1056 +
                                                 (size_t)b_own * 264);
            float4 hreg[8];
#pragma unroll
            for (int r = 0; r < 8; ++r) hreg[r] = hrow[blk + 8 * r];

            float2 acc[2][4][3];
#pragma unroll
            for (int j2 = 0; j2 < 2; ++j2)
#pragma unroll
                for (int b = 0; b < 4; ++b)
#pragma unroll
                    for (int gg = 0; gg < 3; ++gg)
                        acc[j2][b][gg] = make_float2(0.f, 0.f);

#pragma unroll
            for (int i = 0; i < 8; ++i) {
                float4 wv[2][3];
#pragma unroll
                for (int j2 = 0; j2 < 2; ++j2) {
#pragma unroll
                    for (int gg = 0; gg < 3; ++gg)
                        wv[j2][gg] = wp[gg * 4096 + j2 * 64 + 8 * i];
                }
#pragma unroll
                for (int b = 0; b < 4; ++b) {
                    float4 hv = shfl4(hreg[i], (kq << 2) | b);
                    float2 hxy = make_float2(hv.x, hv.y);
                    float2 hzw = make_float2(hv.z, hv.w);
#pragma unroll
                    for (int j2 = 0; j2 < 2; ++j2) {
#pragma unroll
                        for (int gg = 0; gg < 3; ++gg) {
                            acc[j2][b][gg] = ffma2(make_float2(wv[j2][gg].x, wv[j2][gg].y),
                                                   hxy, acc[j2][b][gg]);
                            acc[j2][b][gg] = ffma2(make_float2(wv[j2][gg].z, wv[j2][gg].w),
                                                   hzw, acc[j2][b][gg]);
                        }
                    }
                }
            }

            // horizontal + 8-way xor reduction over kq lanes
            float s[2][4][3];
#pragma unroll
            for (int j2 = 0; j2 < 2; ++j2)
#pragma unroll
                for (int b = 0; b < 4; ++b)
#pragma unroll
                    for (int gg = 0; gg < 3; ++gg) {
                        float v = acc[j2][b][gg].x + acc[j2][b][gg].y;
                        v += __shfl_xor_sync(0xffffffffu, v, 1);
                        v += __shfl_xor_sync(0xffffffffu, v, 2);
                        v += __shfl_xor_sync(0xffffffffu, v, 4);
                        s[j2][b][gg] = v;
                    }

            hr = bh0; hz = bh1; hn = bh2;
#pragma unroll
            for (int j2 = 0; j2 < 2; ++j2)
#pragma unroll
                for (int b = 0; b < 4; ++b)
                    if (kq == ((j2 << 2) | b)) {
                        hr += s[j2][b][0];
                        hz += s[j2][b][1];
                        hn += s[j2][b][2];
                    }
        }

        const float r = sigm(xr + hr);
        const float z = sigm(xz + hz);
        const float n = tanhf(xn + r * hn);
        const float hnew = (1.f - z) * n + z * hprev;
        hprev = hnew;

        __stcg(&seq[((size_t)(b0 + b_out) * TT + t) * ldseq + jgo], hnew);
        if (hlast != nullptr && t == TT - 1)
            __stcg(&hlast[(size_t)(b0 + b_out) * HH + jgo], hnew);

        // broadcast my h value to all 4 CTAs' buffer[t&1]
        const uint32_t po = (uint32_t)(t & 1) * 4224u;      // 1056 floats
        const uint32_t uval = __float_as_uint(hnew);
#pragma unroll
        for (int r2 = 0; r2 < 4; ++r2)
            ST_ASYNC_B32(rh[r2] + po, uval, rm[r2] + (uint32_t)(t & 1) * 8u);
    }

    // drain: consume the final phase so no st.async targets our smem after exit
    MBARRIER_WAIT_PARITY(mb0 + 8, ph1);
    CLUSTER_SYNC();
}

// ---------------- attention (CTA per batch); enc from cat, ctx into cat ----------------
#define AT_SMEM_FLOATS (2 * 64 * 260 + 64 * 68 + 256)
#define AT_SMEM_BYTES  (AT_SMEM_FLOATS * 4)

__global__ void __launch_bounds__(256, 1)
attn_k(const float* __restrict__ Wa, const float* __restrict__ Ua,
       float* __restrict__ cat, const float* __restrict__ va)
{
    extern __shared__ float sm[];
    float* WA = sm;
    float* UA = sm + 64 * 260;
    float* ES = sm + 2 * 64 * 260;
    float* VS = ES + 64 * 68;

    const int b = blockIdx.x;
    const int tid = threadIdx.x;
    const float* waB = Wa + (size_t)b * 64 * 256;
    const float* uaB = Ua + (size_t)b * 64 * 256;

    for (int idx = tid; idx < 4096; idx += 256) {
        int k = idx >> 6, h4 = idx & 63;
        float4 w4 = __ldg((const float4*)waB + idx);
        *(float4*)&WA[k * 260 + ((h4 ^ (k & 7)) << 2)] = w4;   // xor swizzle
        float4 u4 = __ldg((const float4*)uaB + idx);
        *(float4*)&UA[k * 260 + (h4 << 2)] = u4;
    }
    if (tid < 64) *(float4*)&VS[tid * 4] = __ldg((const float4*)va + tid);
    __syncthreads();

    const int tq = tid >> 3, kq = tid & 7;
    const int t0 = tq * 2;
    float e0[8], e1[8];
#pragma unroll
    for (int i = 0; i < 8; ++i) { e0[i] = 0.f; e1[i] = 0.f; }

    for (int h4 = 0; h4 < 64; ++h4) {
        float4 v4 = *(const float4*)&VS[h4 * 4];
        float4 uA = *(const float4*)&UA[t0 * 260 + h4 * 4];
        float4 uB = *(const float4*)&UA[(t0 + 1) * 260 + h4 * 4];
#pragma unroll
        for (int i = 0; i < 8; ++i) {
            int k = i * 8 + kq;
            float4 w4 = *(const float4*)&WA[k * 260 + ((h4 ^ kq) << 2)];
            e0[i] += tanha(w4.x + uA.x) * v4.x + tanha(w4.y + uA.y) * v4.y
                   + tanha(w4.z + uA.z) * v4.z + tanha(w4.w + uA.w) * v4.w;
            e1[i] += tanha(w4.x + uB.x) * v4.x + tanha(w4.y + uB.y) * v4.y
                   + tanha(w4.z + uB.z) * v4.z + tanha(w4.w + uB.w) * v4.w;
        }
    }
#pragma unroll
    for (int i = 0; i < 8; ++i) {
        ES[t0 * 68 + i * 8 + kq] = e0[i];
        ES[(t0 + 1) * 68 + i * 8 + kq] = e1[i];
    }
    __syncthreads();

    // reload enc (cat[:, 0:256]) into WA (plain layout, stride 260)
    for (int idx = tid; idx < 4096; idx += 256) {
        int k = idx >> 6, h4 = idx & 63;
        float4 e4 = __ldg((const float4*)(cat + (size_t)(b * 64 + k) * CATW) + h4);
        *(float4*)&WA[k * 260 + (h4 << 2)] = e4;
    }
    __syncthreads();

    if (tid < 64) {
        float* er = &ES[tid * 68];
        float mx = -1e30f;
        for (int k = 0; k < 64; ++k) mx = fmaxf(mx, er[k]);
        float s = 0.f;
        for (int k = 0; k < 64; ++k) { float e = __expf(er[k] - mx); er[k] = e; s += e; }
        float inv = 1.f / s;
        for (int k = 0; k < 64; ++k) er[k] *= inv;
    }
    __syncthreads();

    const int tq2 = tid >> 4, hq = tid & 15;
    const int tb = tq2 * 4;
    float4 cacc[4][4];
#pragma unroll
    for (int dt = 0; dt < 4; ++dt)
#pragma unroll
        for (int jj = 0; jj < 4; ++jj) cacc[dt][jj] = make_float4(0.f, 0.f, 0.f, 0.f);

    for (int k = 0; k < 64; ++k) {
        float al[4];
#pragma unroll
        for (int dt = 0; dt < 4; ++dt) al[dt] = ES[(tb + dt) * 68 + k];
        float4 ev[4];
#pragma unroll
        for (int jj = 0; jj < 4; ++jj) ev[jj] = *(const float4*)&WA[k * 260 + hq * 16 + jj * 4];
#pragma unroll
        for (int dt = 0; dt < 4; ++dt)
#pragma unroll
            for (int jj = 0; jj < 4; ++jj) cacc[dt][jj] = ffma4(al[dt], ev[jj], cacc[dt][jj]);
    }
    // ctx -> cat[:, 256:512]
#pragma unroll
    for (int dt = 0; dt < 4; ++dt)
#pragma unroll
        for (int jj = 0; jj < 4; ++jj)
            *(float4*)&cat[(size_t)(b * 64 + tb + dt) * CATW + 256 + hq * 16 + jj * 4]
                = cacc[dt][jj];
}

// ---------------- launch ----------------
extern "C" void kernel_launch(void* const* d_in, const int* in_sizes, int n_in,
                              void* d_out, int out_size)
{
    const int*   x     = (const int*)  d_in[0];
    const float* embed = (const float*)d_in[1];
    const float* w_ih0 = (const float*)d_in[2];
    const float* w_hh0 = (const float*)d_in[3];
    const float* b_ih0 = (const float*)d_in[4];
    const float* b_hh0 = (const float*)d_in[5];
    const float* w_ih1 = (const float*)d_in[6];
    const float* w_hh1 = (const float*)d_in[7];
    const float* b_ih1 = (const float*)d_in[8];
    const float* b_hh1 = (const float*)d_in[9];
    const float* W_a   = (const float*)d_in[10];
    const float* U_a   = (const float*)d_in[11];
    const float* v_a   = (const float*)d_in[12];
    const float* fc_W  = (const float*)d_in[13];
    const float* fc_b  = (const float*)d_in[14];

    float* out = (float*)d_out;                 // logits (B,T,V) then h_last (B,H)
    float* hlast = out + (size_t)BB * TT * VV;

    float *xp, *seq, *cat, *wa, *ua;
    cudaGetSymbolAddress((void**)&xp,  g_xp);
    cudaGetSymbolAddress((void**)&seq, g_seq);
    cudaGetSymbolAddress((void**)&cat, g_cat);
    cudaGetSymbolAddress((void**)&wa,  g_Wa);
    cudaGetSymbolAddress((void**)&ua,  g_Ua);

    cudaFuncSetAttribute(attn_k, cudaFuncAttributeMaxDynamicSharedMemorySize, AT_SMEM_BYTES);
    cudaFuncSetAttribute(scan_k, cudaFuncAttributeMaxDynamicSharedMemorySize, SCAN_SMEM_BYTES);

    const int M = BB * TT;  // 8192

    // 1. xp0 = embed[x] @ w_ih0^T + b_ih0    (gather fused)
    gemm128_k<<<dim3(M / 128, G3H / 128), 256>>>(embed, HH, x, w_ih0, HH, b_ih0, xp, G3H, HH);
    // 2. scan layer 0 -> seq (stride 256)
    scan_k<<<128, 256, SCAN_SMEM_BYTES>>>(xp, w_hh0, b_hh0, seq, HH, nullptr);
    // 3. xp1 = seq @ w_ih1^T + b_ih1
    gemm128_k<<<dim3(M / 128, G3H / 128), 256>>>(seq, HH, nullptr, w_ih1, HH, b_ih1, xp, G3H, HH);
    // 4. scan layer 1 -> cat[:, 0:256] (stride 512), h_last
    scan_k<<<128, 256, SCAN_SMEM_BYTES>>>(xp, w_hh1, b_hh1, cat, CATW, hlast);
    // 5. attention projections (both in ONE launch; A = enc inside cat, lda=512)
    gemm_dual_k<<<dim3(M / 128, HH / 128, 2), 256>>>(cat, CATW, W_a, U_a, wa, ua, HH);
    // 6. attention -> ctx into cat[:, 256:512]
    attn_k<<<BB, 256, AT_SMEM_BYTES>>>(wa, ua, cat, v_a);
    // 7. logits = cat @ fc_W^T + fc_b   (single K=512 pass, BM=64 -> 128 CTAs)
    gemm64_k<<<dim3(M / 64, VV / 128), 256>>>(cat, CATW, nullptr, fc_W, 2 * HH, fc_b, out, VV, 2 * HH);
}

// round 17
// speedup vs baseline: 1.1550x; 1.0332x over previous
#include <cuda_runtime.h>
#include <cuda_bf16.h>
#include <cstdint>
#include <cstddef>

#define BB 128
#define TT 64
#define HH 256
#define VV 128
#define G3H 768
#define CATW 512

// ---------------- persistent scratch ----------------
__device__ float g_xp [BB*TT*G3H];     // input projections (both layers, reused)
__device__ float g_seq[BB*TT*HH];      // layer-0 output
__device__ float g_cat[BB*TT*CATW];    // [enc | ctx] concatenated (K=512 fc)
__device__ float g_Wa [BB*TT*HH];
__device__ float g_Ua [BB*TT*HH];

// ---------------- helpers ----------------
union F2U { float2 f; unsigned long long u; };

__device__ __forceinline__ float2 ffma2(float2 a, float2 b, float2 c) {
    F2U A, B, C, D; A.f = a; B.f = b; C.f = c;
    asm("fma.rn.f32x2 %0, %1, %2, %3;" : "=l"(D.u) : "l"(A.u), "l"(B.u), "l"(C.u));
    return D.f;
}

__device__ __forceinline__ float4 ffma4(float a, float4 b, float4 c) {
    float2 p = ffma2(make_float2(a, a), make_float2(b.x, b.y), make_float2(c.x, c.y));
    float2 q = ffma2(make_float2(a, a), make_float2(b.z, b.w), make_float2(c.z, c.w));
    return make_float4(p.x, p.y, q.x, q.y);
}

__device__ __forceinline__ float tanha(float x) {
    float y; asm("tanh.approx.f32 %0, %1;" : "=f"(y) : "f"(x)); return y;
}

__device__ __forceinline__ float sigm(float x) {
    return 1.f / (1.f + __expf(-x));
}

__device__ __forceinline__ uint32_t smem_u32(const void* p) {
    uint32_t a;
    asm("{ .reg .u64 t; cvta.to.shared.u64 t, %1; cvt.u32.u64 %0, t; }" : "=r"(a) : "l"(p));
    return a;
}

#define MBARRIER_INIT(addr, cnt) \
    asm volatile("mbarrier.init.shared.b64 [%0], %1;" :: "r"(addr), "r"(cnt) : "memory")

#define MBARRIER_EXPECT_TX(addr, tx) \
    asm volatile("mbarrier.arrive.expect_tx.shared.b64 _, [%0], %1;" :: "r"(addr), "r"(tx) : "memory")

#define MBARRIER_WAIT_PARITY(addr, par) do {                                        \
    uint32_t _m = (addr); uint32_t _p = (par); uint32_t _done;                      \
    asm volatile("{\n\t.reg .pred p;\n\t"                                           \
        "mbarrier.try_wait.parity.acquire.cta.shared::cta.b64 p, [%1], %2;\n\t"     \
        "selp.b32 %0, 1, 0, p;\n\t}"                                                \
        : "=r"(_done) : "r"(_m), "r"(_p) : "memory");                               \
    if (!_done) {                                                                   \
        asm volatile("{\n\t.reg .pred P1;\n\t"                                      \
            "WL_%=:\n\t"                                                            \
            "mbarrier.try_wait.parity.acquire.cta.shared::cta.b64 P1, [%0], %1, 0x989680;\n\t" \
            "@P1 bra.uni WD_%=;\n\t"                                                \
            "bra.uni WL_%=;\n\t"                                                    \
            "WD_%=:\n\t}" :: "r"(_m), "r"(_p) : "memory");                          \
    }                                                                               \
} while (0)

#define ST_ASYNC_B32(raddr, uval, rmbar) \
    asm volatile("st.async.shared::cluster.mbarrier::complete_tx::bytes.b32 [%0], %1, [%2];" \
        :: "r"(raddr), "r"(uval), "r"(rmbar) : "memory")

#define MAPA_U32(dst, laddr, rank) \
    asm("mapa.shared::cluster.u32 %0, %1, %2;" : "=r"(dst) : "r"(laddr), "r"(rank))

#define CLUSTER_SYNC() do {                                              \
    asm volatile("barrier.cluster.arrive.aligned;" ::: "memory");        \
    asm volatile("barrier.cluster.wait.aligned;" ::: "memory");          \
} while (0)

// ---------------- GEMM body: C[m,n] = sum_k A[m,k]*W[n,k] + bias ----------------
// BM x 128 x 16 tiles, 256 threads, (BM/16) x 8 per thread, f32x2 FMA,
// register-staged prefetch, single-buffered smem (R13-proven mainloop).
// gather != null: A row m is A + gather[m]*lda.
template <int BM>
__device__ __forceinline__ void gemm_body(
    const float* __restrict__ A, int lda, const int* __restrict__ gather,
    const float* __restrict__ W, int ldw,
    const float* __restrict__ bias,
    float* __restrict__ C, int ldc, int K)
{
    constexpr int AP = BM + 4;
    constexpr int MR = BM / 16;          // 8 (BM=128) or 4 (BM=64)
    __shared__ float As[16 * AP];
    __shared__ float Bs[16 * 132];

    const int tid = threadIdx.x;
    const int tx = tid & 15;             // n-octet
    const int ty = tid >> 4;             // m-group
    const int mbase = blockIdx.x * BM;
    const int nbase = blockIdx.y * 128;

    const int ra = tid >> 2;             // 0..63
    const int c4 = tid & 3;              // float4 column within 16-wide k-tile

    const int m0 = mbase + (BM == 128 ? ra : (tid >> 2));
    const float* arow0 = A + (size_t)(gather ? gather[m0] : m0) * lda;
    const float* arow1 = nullptr;
    if (BM == 128) {
        const int m1 = mbase + ra + 64;
        arow1 = A + (size_t)(gather ? gather[m1] : m1) * lda;
    }
    const float* wrow0 = W + (size_t)(nbase + ra) * ldw;
    const float* wrow1 = W + (size_t)(nbase + ra + 64) * ldw;

    float4 acc[MR][2];
#pragma unroll
    for (int i = 0; i < MR; ++i) {
        acc[i][0] = make_float4(0.f, 0.f, 0.f, 0.f);
        acc[i][1] = make_float4(0.f, 0.f, 0.f, 0.f);
    }

    const int ktiles = K >> 4;
    float4 Av0 = __ldg((const float4*)(arow0 + c4 * 4));
    float4 Av1 = make_float4(0.f, 0.f, 0.f, 0.f);
    if (BM == 128) Av1 = __ldg((const float4*)(arow1 + c4 * 4));
    float4 Bv0 = __ldg((const float4*)(wrow0 + c4 * 4));
    float4 Bv1 = __ldg((const float4*)(wrow1 + c4 * 4));

    for (int kt = 0; kt < ktiles; ++kt) {
        // regs -> smem (transposed)
        As[(c4 * 4 + 0) * AP + ra] = Av0.x;
        As[(c4 * 4 + 1) * AP + ra] = Av0.y;
        As[(c4 * 4 + 2) * AP + ra] = Av0.z;
        As[(c4 * 4 + 3) * AP + ra] = Av0.w;
        if (BM == 128) {
            As[(c4 * 4 + 0) * AP + ra + 64] = Av1.x;
            As[(c4 * 4 + 1) * AP + ra + 64] = Av1.y;
            As[(c4 * 4 + 2) * AP + ra + 64] = Av1.z;
            As[(c4 * 4 + 3) * AP + ra + 64] = Av1.w;
        }
        Bs[(c4 * 4 + 0) * 132 + ra]      = Bv0.x;
        Bs[(c4 * 4 + 1) * 132 + ra]      = Bv0.y;
        Bs[(c4 * 4 + 2) * 132 + ra]      = Bv0.z;
        Bs[(c4 * 4 + 3) * 132 + ra]      = Bv0.w;
        Bs[(c4 * 4 + 0) * 132 + ra + 64] = Bv1.x;
        Bs[(c4 * 4 + 1) * 132 + ra + 64] = Bv1.y;
        Bs[(c4 * 4 + 2) * 132 + ra + 64] = Bv1.z;
        Bs[(c4 * 4 + 3) * 132 + ra + 64] = Bv1.w;
        __syncthreads();

        if (kt + 1 < ktiles) {            // prefetch next tile while computing
            Av0 = __ldg((const float4*)(arow0 + (kt + 1) * 16 + c4 * 4));
            if (BM == 128)
                Av1 = __ldg((const float4*)(arow1 + (kt + 1) * 16 + c4 * 4));
            Bv0 = __ldg((const float4*)(wrow0 + (kt + 1) * 16 + c4 * 4));
            Bv1 = __ldg((const float4*)(wrow1 + (kt + 1) * 16 + c4 * 4));
        }

#pragma unroll
        for (int k = 0; k < 16; ++k) {
            float4 b0 = *(const float4*)&Bs[k * 132 + tx * 8];
            float4 b1 = *(const float4*)&Bs[k * 132 + tx * 8 + 4];
            if (BM == 128) {
                float4 a0 = *(const float4*)&As[k * AP + ty * 8];
                float4 a1 = *(const float4*)&As[k * AP + ty * 8 + 4];
                acc[0][0] = ffma4(a0.x, b0, acc[0][0]); acc[0][1] = ffma4(a0.x, b1, acc[0][1]);
                acc[1][0] = ffma4(a0.y, b0, acc[1][0]); acc[1][1] = ffma4(a0.y, b1, acc[1][1]);
                acc[2][0] = ffma4(a0.z, b0, acc[2][0]); acc[2][1] = ffma4(a0.z, b1, acc[2][1]);
                acc[3][0] = ffma4(a0.w, b0, acc[3][0]); acc[3][1] = ffma4(a0.w, b1, acc[3][1]);
                acc[4][0] = ffma4(a1.x, b0, acc[4][0]); acc[4][1] = ffma4(a1.x, b1, acc[4][1]);
                acc[5][0] = ffma4(a1.y, b0, acc[5][0]); acc[5][1] = ffma4(a1.y, b1, acc[5][1]);
                acc[6][0] = ffma4(a1.z, b0, acc[6][0]); acc[6][1] = ffma4(a1.z, b1, acc[6][1]);
                acc[7][0] = ffma4(a1.w, b0, acc[7][0]); acc[7][1] = ffma4(a1.w, b1, acc[7][1]);
            } else {
                float4 a0 = *(const float4*)&As[k * AP + ty * 4];
                acc[0][0] = ffma4(a0.x, b0, acc[0][0]); acc[0][1] = ffma4(a0.x, b1, acc[0][1]);
                acc[1][0] = ffma4(a0.y, b0, acc[1][0]); acc[1][1] = ffma4(a0.y, b1, acc[1][1]);
                acc[2][0] = ffma4(a0.z, b0, acc[2][0]); acc[2][1] = ffma4(a0.z, b1, acc[2][1]);
                acc[3][0] = ffma4(a0.w, b0, acc[3][0]); acc[3][1] = ffma4(a0.w, b1, acc[3][1]);
            }
        }
        __syncthreads();
    }

    const int n0 = nbase + tx * 8;
    float4 bv0 = make_float4(0.f, 0.f, 0.f, 0.f);
    float4 bv1 = bv0;
    if (bias) { bv0 = *(const float4*)&bias[n0]; bv1 = *(const float4*)&bias[n0 + 4]; }
#pragma unroll
    for (int mi = 0; mi < MR; ++mi) {
        int m = mbase + ty * MR + mi;
        float4* cp = (float4*)&C[(size_t)m * ldc + n0];
        float4 o0 = acc[mi][0], o1 = acc[mi][1];
        o0.x += bv0.x; o0.y += bv0.y; o0.z += bv0.z; o0.w += bv0.w;
        o1.x += bv1.x; o1.y += bv1.y; o1.z += bv1.z; o1.w += bv1.w;
        cp[0] = o0; cp[1] = o1;
    }
}

__global__ void __launch_bounds__(256)
gemm128_k(const float* __restrict__ A, int lda, const int* __restrict__ gather,
          const float* __restrict__ W, int ldw, const float* __restrict__ bias,
          float* __restrict__ C, int ldc, int K)
{
    gemm_body<128>(A, lda, gather, W, ldw, bias, C, ldc, K);
}

__global__ void __launch_bounds__(256)
gemm64_k(const float* __restrict__ A, int lda, const int* __restrict__ gather,
         const float* __restrict__ W, int ldw, const float* __restrict__ bias,
         float* __restrict__ C, int ldc, int K)
{
    gemm_body<64>(A, lda, gather, W, ldw, bias, C, ldc, K);
}

// Wa and Ua projections in one launch: blockIdx.z selects (W0->C0) or (W1->C1).
__global__ void __launch_bounds__(256)
gemm_dual_k(const float* __restrict__ A, int lda,
            const float* __restrict__ W0, const float* __restrict__ W1,
            float* __restrict__ C0, float* __restrict__ C1, int K)
{
    const float* W = blockIdx.z ? W1 : W0;
    float*       C = blockIdx.z ? C1 : C0;
    gemm_body<128>(A, lda, nullptr, W, HH, nullptr, C, HH, K);
}

// ---------------- GRU scan: 32 clusters x 4 CTAs ----------------
// Thread (jg8 = tid>>3, kq = tid&7): j-pair {2*jg8, 2*jg8+1} x 4 batches x
// k-float4s {kq + 8i}. Weights read from smem EXACTLY ONCE per CTA per step.
// h read DIRECTLY from smem: for fixed (i,b) the warp's 8 kq-lanes cover one
// 128B contiguous span (all 32 banks once, 4-way jg8 dedup) -> 1 phase per
// LDS.128, no distribution shuffles. 8-way xor-shuffle reduction over kq;
// lane kq finalizes (j2=kq>>2, b=kq&3). h exchanged via st.async.
#define SCAN_WS_BYTES   (3 * 64 * 64 * 16)            // 196608
#define SCAN_HB_FLOATS  (2 * 4 * 264)                 // padded stride 264
#define SCAN_HB_BYTES   (SCAN_HB_FLOATS * 4)          // 8448
#define SCAN_SMEM_BYTES (SCAN_WS_BYTES + SCAN_HB_BYTES + 16)

__global__ void __launch_bounds__(256, 1) __cluster_dims__(4, 1, 1)
scan_k(const float* __restrict__ xp, const float* __restrict__ w_hh,
       const float* __restrict__ b_hh, float* __restrict__ seq, int ldseq,
       float* __restrict__ hlast)
{
    extern __shared__ __align__(16) unsigned char sm_raw[];
    float4* ws = (float4*)sm_raw;                               // [3][64 j][64 f4]
    float*  hb = (float*)(sm_raw + SCAN_WS_BYTES);              // [2][4][264]
    unsigned long long* mbar =
        (unsigned long long*)(sm_raw + SCAN_WS_BYTES + SCAN_HB_BYTES);

    const int g   = blockIdx.x >> 2;
    const int tid = threadIdx.x;
    const int jg8 = tid >> 3;                 // 0..31  j-pair group
    const int kq  = tid & 7;                  // 0..7   k-slice
    const int jl0 = jg8 * 2;
    uint32_t rank;
    asm("mov.u32 %0, %%cluster_ctarank;" : "=r"(rank));
    const int b0 = g * 4;

    // output assignment: lane kq finalizes (j2 = kq>>2, b = kq&3)
    const int j2o   = kq >> 2;
    const int b_out = kq & 3;
    const int jlo   = jl0 + j2o;              // local j of output
    const int jgo   = (int)rank * 64 + jlo;   // global hidden index

    // ---- prologue: copy w_hh slice (row-major, identity in f4) ----
    for (int idx = tid; idx < 3 * 64 * 64; idx += 256) {
        int gg = idx >> 12;
        int jl = (idx >> 6) & 63;
        int f4 = idx & 63;
        ws[idx] = __ldg((const float4*)(w_hh +
                    (size_t)(gg * 256 + (int)rank * 64 + jl) * 256) + f4);
    }

    const float bh0 = b_hh[jgo], bh1 = b_hh[256 + jgo], bh2 = b_hh[512 + jgo];

    const uint32_t mb0 = smem_u32(&mbar[0]);
    const uint32_t myh = smem_u32(&hb[(size_t)b_out * 264 + jgo]);  // parity-0 slot
    uint32_t rh[4], rm[4];
#pragma unroll
    for (int r = 0; r < 4; ++r) { MAPA_U32(rh[r], myh, r); MAPA_U32(rm[r], mb0, r); }

    if (tid == 0) { MBARRIER_INIT(mb0, 1); MBARRIER_INIT(mb0 + 8, 1); }
    __syncthreads();
    CLUSTER_SYNC();                       // all mbars + ws live before any st.async
    if (tid == 0) {
        MBARRIER_EXPECT_TX(mb0, 4096);
        MBARRIER_EXPECT_TX(mb0 + 8, 4096);
    }

    const float* xpb = xp + (size_t)(b0 + b_out) * TT * G3H;
    const float4* wp = ws + (size_t)jl0 * 64 + kq;   // + g*4096 + j2*64 + 8i
    float hprev = 0.f;
    int ph0 = 0, ph1 = 0;

    for (int t = 0; t < TT; ++t) {
        // prefetch xp for this (b_out, t) — hidden under wait + matvec
        const float* xr_p = xpb + (size_t)t * G3H;
        const float xr = __ldcg(xr_p + jgo);
        const float xz = __ldcg(xr_p + 256 + jgo);
        const float xn = __ldcg(xr_p + 512 + jgo);

        float hr, hz, hn;
        if (t == 0) {
            hr = bh0; hz = bh1; hn = bh2;           // h == 0
        } else {
            const int ip = (t - 1) & 1;
            if (ip == 0) { MBARRIER_WAIT_PARITY(mb0, ph0);     ph0 ^= 1; }
            else         { MBARRIER_WAIT_PARITY(mb0 + 8, ph1); ph1 ^= 1; }
            if (tid == 0) MBARRIER_EXPECT_TX(mb0 + 8 * ip, 4096);  // re-arm

            const float* hrow = hb + (size_t)ip * 1056;

            float2 acc[2][4][3];
#pragma unroll
            for (int j2 = 0; j2 < 2; ++j2)
#pragma unroll
                for (int b = 0; b < 4; ++b)
#pragma unroll
                    for (int gg = 0; gg < 3; ++gg)
                        acc[j2][b][gg] = make_float2(0.f, 0.f);

#pragma unroll
            for (int i = 0; i < 8; ++i) {
                float4 wv[2][3];
#pragma unroll
                for (int j2 = 0; j2 < 2; ++j2) {
#pragma unroll
                    for (int gg = 0; gg < 3; ++gg)
                        wv[j2][gg] = wp[gg * 4096 + j2 * 64 + 8 * i];
                }
#pragma unroll
                for (int b = 0; b < 4; ++b) {
                    // 128B contiguous across the warp's kq-lanes: 1 phase
                    float4 hv = *(const float4*)&hrow[b * 264 + (kq + 8 * i) * 4];
                    float2 hxy = make_float2(hv.x, hv.y);
                    float2 hzw = make_float2(hv.z, hv.w);
#pragma unroll
                    for (int j2 = 0; j2 < 2; ++j2) {
#pragma unroll
                        for (int gg = 0; gg < 3; ++gg) {
                            acc[j2][b][gg] = ffma2(make_float2(wv[j2][gg].x, wv[j2][gg].y),
                                                   hxy, acc[j2][b][gg]);
                            acc[j2][b][gg] = ffma2(make_float2(wv[j2][gg].z, wv[j2][gg].w),
                                                   hzw, acc[j2][b][gg]);
                        }
                    }
                }
            }

            // horizontal + 8-way xor reduction over kq lanes
            float s[2][4][3];
#pragma unroll
            for (int j2 = 0; j2 < 2; ++j2)
#pragma unroll
                for (int b = 0; b < 4; ++b)
#pragma unroll
                    for (int gg = 0; gg < 3; ++gg) {
                        float v = acc[j2][b][gg].x + acc[j2][b][gg].y;
                        v += __shfl_xor_sync(0xffffffffu, v, 1);
                        v += __shfl_xor_sync(0xffffffffu, v, 2);
                        v += __shfl_xor_sync(0xffffffffu, v, 4);
                        s[j2][b][gg] = v;
                    }

            hr = bh0; hz = bh1; hn = bh2;
#pragma unroll
            for (int j2 = 0; j2 < 2; ++j2)
#pragma unroll
                for (int b = 0; b < 4; ++b)
                    if (kq == ((j2 << 2) | b)) {
                        hr += s[j2][b][0];
                        hz += s[j2][b][1];
                        hn += s[j2][b][2];
                    }
        }

        const float r = sigm(xr + hr);
        const float z = sigm(xz + hz);
        const float n = tanhf(xn + r * hn);
        const float hnew = (1.f - z) * n + z * hprev;
        hprev = hnew;

        __stcg(&seq[((size_t)(b0 + b_out) * TT + t) * ldseq + jgo], hnew);
        if (hlast != nullptr && t == TT - 1)
            __stcg(&hlast[(size_t)(b0 + b_out) * HH + jgo], hnew);

        // broadcast my h value to all 4 CTAs' buffer[t&1]
        const uint32_t po = (uint32_t)(t & 1) * 4224u;      // 1056 floats
        const uint32_t uval = __float_as_uint(hnew);
#pragma unroll
        for (int r2 = 0; r2 < 4; ++r2)
            ST_ASYNC_B32(rh[r2] + po, uval, rm[r2] + (uint32_t)(t & 1) * 8u);
    }

    // drain: consume the final phase so no st.async targets our smem after exit
    MBARRIER_WAIT_PARITY(mb0 + 8, ph1);
    CLUSTER_SYNC();
}

// ---------------- attention (CTA per batch); enc from cat, ctx into cat ----------------
#define AT_SMEM_FLOATS (2 * 64 * 260 + 64 * 68 + 256)
#define AT_SMEM_BYTES  (AT_SMEM_FLOATS * 4)

__global__ void __launch_bounds__(256, 1)
attn_k(const float* __restrict__ Wa, const float* __restrict__ Ua,
       float* __restrict__ cat, const float* __restrict__ va)
{
    extern __shared__ float sm[];
    float* WA = sm;
    float* UA = sm + 64 * 260;
    float* ES = sm + 2 * 64 * 260;
    float* VS = ES + 64 * 68;

    const int b = blockIdx.x;
    const int tid = threadIdx.x;
    const float* waB = Wa + (size_t)b * 64 * 256;
    const float* uaB = Ua + (size_t)b * 64 * 256;

    for (int idx = tid; idx < 4096; idx += 256) {
        int k = idx >> 6, h4 = idx & 63;
        float4 w4 = __ldg((const float4*)waB + idx);
        *(float4*)&WA[k * 260 + ((h4 ^ (k & 7)) << 2)] = w4;   // xor swizzle
        float4 u4 = __ldg((const float4*)uaB + idx);
        *(float4*)&UA[k * 260 + (h4 << 2)] = u4;
    }
    if (tid < 64) *(float4*)&VS[tid * 4] = __ldg((const float4*)va + tid);
    __syncthreads();

    const int tq = tid >> 3, kq = tid & 7;
    const int t0 = tq * 2;
    float e0[8], e1[8];
#pragma unroll
    for (int i = 0; i < 8; ++i) { e0[i] = 0.f; e1[i] = 0.f; }

    for (int h4 = 0; h4 < 64; ++h4) {
        float4 v4 = *(const float4*)&VS[h4 * 4];
        float4 uA = *(const float4*)&UA[t0 * 260 + h4 * 4];
        float4 uB = *(const float4*)&UA[(t0 + 1) * 260 + h4 * 4];
#pragma unroll
        for (int i = 0; i < 8; ++i) {
            int k = i * 8 + kq;
            float4 w4 = *(const float4*)&WA[k * 260 + ((h4 ^ kq) << 2)];
            e0[i] += tanha(w4.x + uA.x) * v4.x + tanha(w4.y + uA.y) * v4.y
                   + tanha(w4.z + uA.z) * v4.z + tanha(w4.w + uA.w) * v4.w;
            e1[i] += tanha(w4.x + uB.x) * v4.x + tanha(w4.y + uB.y) * v4.y
                   + tanha(w4.z + uB.z) * v4.z + tanha(w4.w + uB.w) * v4.w;
        }
    }
#pragma unroll
    for (int i = 0; i < 8; ++i) {
        ES[t0 * 68 + i * 8 + kq] = e0[i];
        ES[(t0 + 1) * 68 + i * 8 + kq] = e1[i];
    }
    __syncthreads();

    // reload enc (cat[:, 0:256]) into WA (plain layout, stride 260)
    for (int idx = tid; idx < 4096; idx += 256) {
        int k = idx >> 6, h4 = idx & 63;
        float4 e4 = __ldg((const float4*)(cat + (size_t)(b * 64 + k) * CATW) + h4);
        *(float4*)&WA[k * 260 + (h4 << 2)] = e4;
    }
    __syncthreads();

    if (tid < 64) {
        float* er = &ES[tid * 68];
        float mx = -1e30f;
        for (int k = 0; k < 64; ++k) mx = fmaxf(mx, er[k]);
        float s = 0.f;
        for (int k = 0; k < 64; ++k) { float e = __expf(er[k] - mx); er[k] = e; s += e; }
        float inv = 1.f / s;
        for (int k = 0; k < 64; ++k) er[k] *= inv;
    }
    __syncthreads();

    const int tq2 = tid >> 4, hq = tid & 15;
    const int tb = tq2 * 4;
    float4 cacc[4][4];
#pragma unroll
    for (int dt = 0; dt < 4; ++dt)
#pragma unroll
        for (int jj = 0; jj < 4; ++jj) cacc[dt][jj] = make_float4(0.f, 0.f, 0.f, 0.f);

    for (int k = 0; k < 64; ++k) {
        float al[4];
#pragma unroll
        for (int dt = 0; dt < 4; ++dt) al[dt] = ES[(tb + dt) * 68 + k];
        float4 ev[4];
#pragma unroll
        for (int jj = 0; jj < 4; ++jj) ev[jj] = *(const float4*)&WA[k * 260 + hq * 16 + jj * 4];
#pragma unroll
        for (int dt = 0; dt < 4; ++dt)
#pragma unroll
            for (int jj = 0; jj < 4; ++jj) cacc[dt][jj] = ffma4(al[dt], ev[jj], cacc[dt][jj]);
    }
    // ctx -> cat[:, 256:512]
#pragma unroll
    for (int dt = 0; dt < 4; ++dt)
#pragma unroll
        for (int jj = 0; jj < 4; ++jj)
            *(float4*)&cat[(size_t)(b * 64 + tb + dt) * CATW + 256 + hq * 16 + jj * 4]
                = cacc[dt][jj];
}

// ---------------- launch ----------------
extern "C" void kernel_launch(void* const* d_in, const int* in_sizes, int n_in,
                              void* d_out, int out_size)
{
    const int*   x     = (const int*)  d_in[0];
    const float* embed = (const float*)d_in[1];
    const float* w_ih0 = (const float*)d_in[2];
    const float* w_hh0 = (const float*)d_in[3];
    const float* b_ih0 = (const float*)d_in[4];
    const float* b_hh0 = (const float*)d_in[5];
    const float* w_ih1 = (const float*)d_in[6];
    const float* w_hh1 = (const float*)d_in[7];
    const float* b_ih1 = (const float*)d_in[8];
    const float* b_hh1 = (const float*)d_in[9];
    const float* W_a   = (const float*)d_in[10];
    const float* U_a   = (const float*)d_in[11];
    const float* v_a   = (const float*)d_in[12];
    const float* fc_W  = (const float*)d_in[13];
    const float* fc_b  = (const float*)d_in[14];

    float* out = (float*)d_out;                 // logits (B,T,V) then h_last (B,H)
    float* hlast = out + (size_t)BB * TT * VV;

    float *xp, *seq, *cat, *wa, *ua;
    cudaGetSymbolAddress((void**)&xp,  g_xp);
    cudaGetSymbolAddress((void**)&seq, g_seq);
    cudaGetSymbolAddress((void**)&cat, g_cat);
    cudaGetSymbolAddress((void**)&wa,  g_Wa);
    cudaGetSymbolAddress((void**)&ua,  g_Ua);

    cudaFuncSetAttribute(attn_k, cudaFuncAttributeMaxDynamicSharedMemorySize, AT_SMEM_BYTES);
    cudaFuncSetAttribute(scan_k, cudaFuncAttributeMaxDynamicSharedMemorySize, SCAN_SMEM_BYTES);

    const int M = BB * TT;  // 8192

    // 1. xp0 = embed[x] @ w_ih0^T + b_ih0    (gather fused)
    gemm128_k<<<dim3(M / 128, G3H / 128), 256>>>(embed, HH, x, w_ih0, HH, b_ih0, xp, G3H, HH);
    // 2. scan layer 0 -> seq (stride 256)
    scan_k<<<128, 256, SCAN_SMEM_BYTES>>>(xp, w_hh0, b_hh0, seq, HH, nullptr);
    // 3. xp1 = seq @ w_ih1^T + b_ih1
    gemm128_k<<<dim3(M / 128, G3H / 128), 256>>>(seq, HH, nullptr, w_ih1, HH, b_ih1, xp, G3H, HH);
    // 4. scan layer 1 -> cat[:, 0:256] (stride 512), h_last
    scan_k<<<128, 256, SCAN_SMEM_BYTES>>>(xp, w_hh1, b_hh1, cat, CATW, hlast);
    // 5. attention projections (both in ONE launch; A = enc inside cat, lda=512)
    gemm_dual_k<<<dim3(M / 128, HH / 128, 2), 256>>>(cat, CATW, W_a, U_a, wa, ua, HH);
    // 6. attention -> ctx into cat[:, 256:512]
    attn_k<<<BB, 256, AT_SMEM_BYTES>>>(wa, ua, cat, v_a);
    // 7. logits = cat @ fc_W^T + fc_b   (single K=512 pass, BM=64 -> 128 CTAs)
    gemm64_k<<<dim3(M / 64, VV / 128), 256>>>(cat, CATW, nullptr, fc_W, 2 * HH, fc_b, out, VV, 2 * HH);
}